// round 2
// baseline (speedup 1.0000x reference)
#include <cuda_runtime.h>
#include <cuda_bf16.h>

// Single-particle RK4 undulator tracker.
// Key analytic facts exploited (all verified against the reference math):
//   * dp/dt = -p x B / gamma with B = (0, B0 cos(ku z), 0)
//       => dp_y/dt == 0 exactly, and p . dp/dt == 0 exactly  => |p|, gamma invariant.
//   * RK4's violation of the quadratic invariant is O((w*dt)^5) ~ 3e-22/step,
//     far below f32 eps, so gamma == gamma_0 to below f32 precision for the
//     whole run. We therefore hoist 1/gamma and 1/(C*gamma) (beta scale) as
//     constants, deleting the per-stage |p|^2 / sqrt / divide chain.
//   * cos(ku z) with z up to ~3100: maintained incrementally as a unit vector
//     (cos psi, sin psi) rotated by the small per-step angle ku*dz (<= 0.006
//     rad; 2-term sin / 1-term cos polynomials are exact to f32), with a
//     1-Newton renormalization per step. Per-stage field values use the same
//     small-angle rotation off the step's base phase.

__global__ void __launch_bounds__(32, 1) track_seq_kernel(
    const float* __restrict__ time,
    const float* __restrict__ r0v,
    const float* __restrict__ d0v,
    const float* __restrict__ gptr,
    const float* __restrict__ b0ptr,
    const float* __restrict__ kuptr,
    float* __restrict__ out, int N)
{
    if (threadIdx.x != 0 || blockIdx.x != 0) return;

    const float C   = 0.29979245f;
    const float dt  = time[1] - time[0];
    const float dt2 = 0.5f * dt;
    const float h6  = dt * (1.0f / 6.0f);

    const float gamma = gptr[0];
    const float B0    = b0ptr[0];
    const float ku    = kuptr[0];

    const float A      = 1.0f / gamma;        // 1/gamma (invariant)
    const float KdtA2  = ku * dt2 * A;        // phase delta per unit pz, half step
    const float KdtA   = ku * dt  * A;        // phase delta per unit pz, full step
    const float inv_cg = 1.0f / (C * gamma);  // beta = p * inv_cg (|p| invariant)

    // Initial momentum: p0 = C*sqrt(gamma^2-1) * d0/|d0|
    float dx0 = d0v[0], dy0 = d0v[1], dz0 = d0v[2];
    float dn = sqrtf(dx0 * dx0 + dy0 * dy0 + dz0 * dz0);
    float ps = C * sqrtf(gamma * gamma - 1.0f) / dn;
    float px = ps * dx0, py = ps * dy0, pz = ps * dz0;

    float x = r0v[0], y = r0v[1], z = r0v[2];

    const float vy = py * A;  // p_y exactly constant -> y is linear drift

    // Field phase state
    float cps = cosf(ku * z);
    float sps = sinf(ku * z);
    float Bc = B0 * cps, Bs = B0 * sps;

    const size_t Ns = (size_t)N;
    // t = 0 outputs
    out[0]          = x;
    out[Ns]         = y;
    out[2 * Ns]     = z;
    out[3 * Ns]     = px * inv_cg;
    out[4 * Ns]     = py * inv_cg;
    out[5 * Ns]     = pz * inv_cg;

    #pragma unroll 1
    for (int i = 1; i < N; ++i) {
        // ---- stage 1 (at base z, base p) ----
        float vx1 = px * A, vz1 = pz * A;
        float apx1 =  pz * Bc * A;
        float apz1 = -px * Bc * A;

        // ---- stage 2 (z + vz1*dt2, p + k1*dt2) ----
        float px2 = fmaf(apx1, dt2, px);
        float pz2 = fmaf(apz1, dt2, pz);
        float d2  = KdtA2 * pz;                     // ku * vz1 * dt2
        float q2  = d2 * d2;
        float sd2 = d2 * fmaf(-0.16666667f, q2, 1.0f);
        float cd2 = fmaf(-0.5f, q2, 1.0f);
        float By2 = fmaf(Bc, cd2, -Bs * sd2);       // B0*cos(psi + d2)
        float vx2 = px2 * A, vz2 = pz2 * A;
        float apx2 =  pz2 * By2 * A;
        float apz2 = -px2 * By2 * A;

        // ---- stage 3 (z + vz2*dt2, p + k2*dt2) ----
        float px3 = fmaf(apx2, dt2, px);
        float pz3 = fmaf(apz2, dt2, pz);
        float d3  = KdtA2 * pz2;
        float q3  = d3 * d3;
        float sd3 = d3 * fmaf(-0.16666667f, q3, 1.0f);
        float cd3 = fmaf(-0.5f, q3, 1.0f);
        float By3 = fmaf(Bc, cd3, -Bs * sd3);
        float vx3 = px3 * A, vz3 = pz3 * A;
        float apx3 =  pz3 * By3 * A;
        float apz3 = -px3 * By3 * A;

        // ---- stage 4 (z + vz3*dt, p + k3*dt) ----
        float px4 = fmaf(apx3, dt, px);
        float pz4 = fmaf(apz3, dt, pz);
        float d4  = KdtA * pz3;
        float q4  = d4 * d4;
        float sd4 = d4 * fmaf(-0.16666667f, q4, 1.0f);
        float cd4 = fmaf(-0.5f, q4, 1.0f);
        float By4 = fmaf(Bc, cd4, -Bs * sd4);
        float vx4 = px4 * A, vz4 = pz4 * A;
        float apx4 =  pz4 * By4 * A;
        float apz4 = -px4 * By4 * A;

        // ---- RK4 combine ----
        float dxs = h6 * (vx1 + 2.0f * (vx2 + vx3) + vx4);
        float dzs = h6 * (vz1 + 2.0f * (vz2 + vz3) + vz4);
        px = px + h6 * (apx1 + 2.0f * (apx2 + apx3) + apx4);
        pz = pz + h6 * (apz1 + 2.0f * (apz2 + apz3) + apz4);
        x += dxs;
        y += dt * vy;
        z += dzs;

        // ---- rotate field phase by ku*dzs, renormalize ----
        float dp  = ku * dzs;                       // ~0.006 rad
        float qp  = dp * dp;
        float sdp = dp * fmaf(-0.16666667f, qp, 1.0f);
        float cdp = fmaf(-0.5f, qp, 1.0f);
        float cn  = fmaf(cps, cdp, -sps * sdp);
        float sn  = fmaf(sps, cdp,  cps * sdp);
        float nr   = fmaf(cn, cn, sn * sn);
        float corr = fmaf(-0.5f, nr, 1.5f);
        cps = cn * corr;
        sps = sn * corr;
        Bc = B0 * cps;
        Bs = B0 * sps;

        // ---- outputs ----
        out[i]          = x;
        out[Ns + i]     = y;
        out[2 * Ns + i] = z;
        out[3 * Ns + i] = px * inv_cg;
        out[4 * Ns + i] = py * inv_cg;
        out[5 * Ns + i] = pz * inv_cg;
    }
}

extern "C" void kernel_launch(void* const* d_in, const int* in_sizes, int n_in,
                              void* d_out, int out_size) {
    const float* time = (const float*)d_in[0];
    const float* r0   = (const float*)d_in[1];
    const float* d0   = (const float*)d_in[2];
    const float* gam  = (const float*)d_in[3];
    const float* B0   = (const float*)d_in[4];
    const float* ku   = (const float*)d_in[5];
    float* out = (float*)d_out;
    int N = in_sizes[0];

    track_seq_kernel<<<1, 32>>>(time, r0, d0, gam, B0, ku, out, N);
}

// round 4
// speedup vs baseline: 63.6887x; 63.6887x over previous
#include <cuda_runtime.h>
#include <cuda_bf16.h>

// Parallel-in-time undulator tracker replicating the reference's f32
// accumulation behavior.
//
// Physics structure: gamma, |p|, py exactly invariant; (px,pz) is a rotation
// by theta(t) = (B0/gamma) int cos(ku z) dt. The reference's f32 state
// accumulation z += c quantizes c to ulp(z) (c/ulp ~ 12 in the top binade!),
// a large deterministic bias we must replicate. Within a binade,
// fl(z+c)-z = u*RN(c/u), independent of z's low bits -> parallelizable as a
// prefix sum of pointwise-quantized increments. Picard-iterate the
// z <-> field-phase fixpoint (weakly contracting); each sweep = one f64 scan
// (theta) + one quantized scan (z). Final sweep adds quantized x,y scans and
// writes outputs. p/gamma quantization is gamma-suppressed (dvz/dpz ~ 2e-6)
// and skipped.

#define TPB  512
#define EPT  4
#define TILE (TPB * EPT)      // 2048
#define GMAX 512
#define NCH  5
#define NMAXE (1 << 20)

__device__ double g_zarr[NMAXE];
__device__ double g_agg[NCH][2][GMAX];
__device__ double g_pre[NCH][2][GMAX];
__device__ volatile int g_flag[NCH][2][GMAX];

static __device__ __forceinline__ double warp_scan_incl(double v, int lane) {
#pragma unroll
    for (int d = 1; d < 32; d <<= 1) {
        double n = __shfl_up_sync(0xffffffffu, v, d);
        if (lane >= d) v += n;
    }
    return v;
}

static __device__ __forceinline__ double warp_sum(double v) {
#pragma unroll
    for (int d = 16; d; d >>= 1) v += __shfl_down_sync(0xffffffffu, v, d);
    return __shfl_sync(0xffffffffu, v, 0);
}

// Exclusive prefix over predecessor blocks (warp-0 collective, windowed lookback).
static __device__ double lookback_chain(int c, int q, int b, int lane) {
    double ex = 0.0;
    int hi = b;
    while (hi > 0) {
        int lo = hi - 32; if (lo < 0) lo = 0;
        int cnt = hi - lo;
        int idx = lo + lane;
        int fl = 1;
        if (lane < cnt) {
            do { fl = g_flag[c][q][idx]; } while (fl == 0);
        }
        __threadfence();
        double val = 0.0;
        if (lane < cnt) {
            val = (fl == 2) ? *(volatile double*)&g_pre[c][q][idx]
                            : *(volatile double*)&g_agg[c][q][idx];
        }
        unsigned pm = __ballot_sync(0xffffffffu, (lane < cnt) && (fl == 2));
        if (pm) {
            int h = 31 - __clz(pm);   // highest lane with full prefix
            double contrib = (lane >= h && lane < cnt) ? val : 0.0;
            ex += warp_sum(contrib);
            break;
        } else {
            double contrib = (lane < cnt) ? val : 0.0;
            ex += warp_sum(contrib);
            hi = lo;
        }
    }
    return ex;
}

// Block scan + lookback for chain c. Input: this thread's local total.
// Returns this thread's global EXCLUSIVE prefix.
static __device__ double scan_chain(double ttot, int c, int q, int b,
                                    double* s_warp, double* s_bcast,
                                    int tid, int lane, int wid)
{
    __syncthreads();   // protect s_warp/s_bcast reuse across calls
    double wi = warp_scan_incl(ttot, lane);
    if (lane == 31) s_warp[wid] = wi;
    __syncthreads();
    if (wid == 0) {
        const int nw = TPB / 32;
        double v  = (lane < nw) ? s_warp[lane] : 0.0;
        double sc = warp_scan_incl(v, lane);
        double btot = __shfl_sync(0xffffffffu, sc, nw - 1);
        if (lane < nw) s_warp[lane] = sc - v;
        if (lane == 0) {
            *(volatile double*)&g_agg[c][q][b] = btot;
            __threadfence();
            g_flag[c][q][b] = 1;
        }
        double ex = lookback_chain(c, q, b, lane);
        if (lane == 0) {
            *(volatile double*)&g_pre[c][q][b] = ex + btot;
            __threadfence();
            g_flag[c][q][b] = 2;
            *s_bcast = ex;
        }
    }
    __syncthreads();
    return *s_bcast + s_warp[wid] + (wi - ttot);
}

static __device__ __forceinline__ void sincos_small(double th, double& s, double& c) {
    double t2 = th * th;
    s = th * (1.0 - t2 * (1.0 / 6.0) * (1.0 - t2 * (1.0 / 20.0)));
    c = 1.0 - 0.5 * t2 * (1.0 - t2 * (1.0 / 12.0));
}

// f32-replicated field value at z: psi = fl32(ku * fl32(z)), then
// f64 Cody-Waite reduction + cosf (matches libdevice cosf to ~ulps).
static __device__ __forceinline__ double fval(double zi, float kuf) {
    const double INV2PI = 0.15915494309189535;
    const double TWOPI  = 6.283185307179586;
    float psif = __fmul_rn(kuf, (float)zi);
    double psi = (double)psif;
    double w = fma(-TWOPI, rint(psi * INV2PI), psi);
    return (double)cosf((float)w);
}

// Quantized increment: what fl32(ref + c) - ref would add, given ref's binade.
static __device__ __forceinline__ double qstep(double c, double ref) {
    float f = fabsf((float)ref);
    unsigned bb = __float_as_uint(f);
    int e = (int)((bb >> 23) & 0xff);
    if (e == 0) return c;                 // subnormal region: ulp negligible
    double u    = ldexp(1.0, e - 150);    // 2^(e-127-23)
    double invu = ldexp(1.0, 150 - e);
    return u * rint(c * invu);
}

// mode: 0 = init (ballistic z), 1 = Picard iteration, 2 = final (outputs)
__global__ void __launch_bounds__(TPB, 1) picard_kernel(
    const float* __restrict__ time, const float* __restrict__ r0v,
    const float* __restrict__ d0v, const float* __restrict__ gptr,
    const float* __restrict__ b0ptr, const float* __restrict__ kuptr,
    float* __restrict__ out, int N, int mode, int parity)
{
    __shared__ double s_warp[TPB / 32 + 1];
    __shared__ double s_bcast;

    const int tid = threadIdx.x;
    const int lane = tid & 31, wid = tid >> 5;
    const int b = blockIdx.x, q = parity;

    if (tid < NCH) g_flag[tid][1 - q][b] = 0;   // reset for next launch

    // ---- scalars (f32-replicated initial momentum) ----
    const double Cc = 0.29979245;
    const double dt = (double)(time[1] - time[0]);
    const double gamma = (double)gptr[0];
    const double B0 = (double)b0ptr[0];
    const float  kuf = kuptr[0];
    float dxf = d0v[0], dyf = d0v[1], dzf = d0v[2];
    float gf = gptr[0];
    float dnf = sqrtf(dxf * dxf + dyf * dyf + dzf * dzf);
    float csf = 0.29979245f * sqrtf(gf * gf - 1.0f);
    double px0 = (double)(csf * dxf / dnf);
    double py0 = (double)(csf * dyf / dnf);
    double pz0 = (double)(csf * dzf / dnf);
    double x0 = (double)r0v[0], y0 = (double)r0v[1], z0 = (double)r0v[2];
    double invg = 1.0 / gamma;
    double Kth = B0 * dt * invg;
    double invcg = 1.0 / (Cc * gamma);
    double vz0 = pz0 * invg;
    double f0 = fval(z0, kuf);
    double cy = dt * py0 * invg;     // exact constant y increment

    int base = b * TILE + tid * EPT;

    double af[EPT], ap[EPT], az[EPT], ath[EPT], aq[EPT];

    // ---- phase A: field f_i = cos(ku * zhat_i) ----
    double run = 0.0;
#pragma unroll
    for (int k = 0; k < EPT; ++k) {
        int i = base + k;
        double f = 0.0, zi = z0;
        if (i < N) {
            zi = (mode == 0) ? (z0 + vz0 * (dt * (double)i)) : g_zarr[i];
            f = fval(zi, kuf);
        }
        az[k] = zi;
        run += f;
        af[k] = f;
        ap[k] = run;
    }
    double exf = scan_chain(run, 0, q, b, s_warp, &s_bcast, tid, lane, wid);

    // ---- phase B: theta, midpoint vz, quantized z increment ----
    run = 0.0;
#pragma unroll
    for (int k = 0; k < EPT; ++k) {
        int i = base + k;
        double P = exf + ap[k];                        // inclusive prefix of f
        double th = Kth * (P - 0.5 * (f0 + af[k]));    // cumtrapz theta at node
        ath[k] = th;
        double qz = 0.0;
        if (i < N) {
            double thm = th + 0.5 * Kth * af[k];       // theta at edge midpoint
            double s, c; sincos_small(thm, s, c);
            double cz = dt * (pz0 * c - px0 * s) * invg;
            qz = qstep(cz, az[k]);
        }
        run += qz;
        aq[k] = qz;
        ap[k] = run;
    }
    double exq = scan_chain(run, 1, q, b, s_warp, &s_bcast, tid, lane, wid);

    if (mode != 2) {
#pragma unroll
        for (int k = 0; k < EPT; ++k) {
            int i = base + k;
            if (i < N) g_zarr[i] = z0 + exq + (ap[k] - aq[k]);   // exclusive
        }
        return;
    }

    // ================= final pass =================
    double azn[EPT], acx[EPT], arx[EPT], aqy[EPT];
#pragma unroll
    for (int k = 0; k < EPT; ++k)
        azn[k] = z0 + exq + (ap[k] - aq[k]);           // quantized z output

    // x: plain scan of c_x for binade estimate, then quantized scan
    run = 0.0;
#pragma unroll
    for (int k = 0; k < EPT; ++k) {
        int i = base + k;
        double cx = 0.0;
        if (i < N) {
            double thm = ath[k] + 0.5 * Kth * af[k];
            double s, c; sincos_small(thm, s, c);
            cx = dt * (px0 * c + pz0 * s) * invg;
        }
        acx[k] = cx;
        run += cx;
        ap[k] = run;
    }
    double excx = scan_chain(run, 2, q, b, s_warp, &s_bcast, tid, lane, wid);

    run = 0.0;
#pragma unroll
    for (int k = 0; k < EPT; ++k) {
        double xplain = x0 + excx + (ap[k] - acx[k]);  // exclusive plain x
        double qx = (base + k < N) ? qstep(acx[k], xplain) : 0.0;
        af[k] = qx;            // reuse af for qx
        run += qx;
        arx[k] = run;
    }
    double exqx = scan_chain(run, 3, q, b, s_warp, &s_bcast, tid, lane, wid);

    // y: plain value closed-form (constant increment), then quantized scan
    run = 0.0;
#pragma unroll
    for (int k = 0; k < EPT; ++k) {
        int i = base + k;
        double yplain = y0 + cy * (double)i;
        double qy = (i < N) ? qstep(cy, yplain) : 0.0;
        aqy[k] = qy;
        run += qy;
        ap[k] = run;           // reuse ap for qy running
    }
    double exqy = scan_chain(run, 4, q, b, s_warp, &s_bcast, tid, lane, wid);

    size_t Ns = (size_t)N;
#pragma unroll
    for (int k = 0; k < EPT; ++k) {
        int i = base + k;
        if (i < N) {
            double s, c; sincos_small(ath[k], s, c);
            double px = px0 * c + pz0 * s;
            double pz = pz0 * c - px0 * s;
            double xh = x0 + exqx + (arx[k] - af[k]);
            double yh = y0 + exqy + (ap[k] - aqy[k]);
            out[i]          = (float)xh;
            out[Ns + i]     = (float)yh;
            out[2 * Ns + i] = (float)azn[k];
            out[3 * Ns + i] = (float)(px * invcg);
            out[4 * Ns + i] = (float)(py0 * invcg);
            out[5 * Ns + i] = (float)(pz * invcg);
        }
    }
}

// ---------------- serial fallback (N exceeds scratch capacity) -------------
__global__ void __launch_bounds__(32, 1) track_seq_kernel(
    const float* __restrict__ time, const float* __restrict__ r0v,
    const float* __restrict__ d0v, const float* __restrict__ gptr,
    const float* __restrict__ b0ptr, const float* __restrict__ kuptr,
    float* __restrict__ out, int N)
{
    if (threadIdx.x != 0 || blockIdx.x != 0) return;
    const float C = 0.29979245f;
    const float dt = time[1] - time[0];
    const float dt2 = 0.5f * dt, h6 = dt * (1.0f / 6.0f);
    const float gamma = gptr[0], B0 = b0ptr[0], ku = kuptr[0];
    const float A = 1.0f / gamma;
    const float KdtA2 = ku * dt2 * A, KdtA = ku * dt * A;
    const float inv_cg = 1.0f / (C * gamma);
    float dx0 = d0v[0], dy0 = d0v[1], dz0 = d0v[2];
    float dn = sqrtf(dx0 * dx0 + dy0 * dy0 + dz0 * dz0);
    float pscale = C * sqrtf(gamma * gamma - 1.0f) / dn;
    float px = pscale * dx0, py = pscale * dy0, pz = pscale * dz0;
    float x = r0v[0], y = r0v[1], z = r0v[2];
    const float vy = py * A;
    float cps = cosf(ku * z), sps = sinf(ku * z);
    float Bc = B0 * cps, Bs = B0 * sps;
    const size_t Ns = (size_t)N;
    out[0] = x; out[Ns] = y; out[2 * Ns] = z;
    out[3 * Ns] = px * inv_cg; out[4 * Ns] = py * inv_cg; out[5 * Ns] = pz * inv_cg;
#pragma unroll 1
    for (int i = 1; i < N; ++i) {
        float vx1 = px * A, vz1 = pz * A;
        float apx1 = pz * Bc * A, apz1 = -px * Bc * A;
        float px2 = fmaf(apx1, dt2, px), pz2 = fmaf(apz1, dt2, pz);
        float d2 = KdtA2 * pz, q2 = d2 * d2;
        float sd2 = d2 * fmaf(-0.16666667f, q2, 1.0f), cd2 = fmaf(-0.5f, q2, 1.0f);
        float By2 = fmaf(Bc, cd2, -Bs * sd2);
        float vx2 = px2 * A, vz2 = pz2 * A;
        float apx2 = pz2 * By2 * A, apz2 = -px2 * By2 * A;
        float px3 = fmaf(apx2, dt2, px), pz3 = fmaf(apz2, dt2, pz);
        float d3 = KdtA2 * pz2, q3 = d3 * d3;
        float sd3 = d3 * fmaf(-0.16666667f, q3, 1.0f), cd3 = fmaf(-0.5f, q3, 1.0f);
        float By3 = fmaf(Bc, cd3, -Bs * sd3);
        float vx3 = px3 * A, vz3 = pz3 * A;
        float apx3 = pz3 * By3 * A, apz3 = -px3 * By3 * A;
        float px4 = fmaf(apx3, dt, px), pz4 = fmaf(apz3, dt, pz);
        float d4 = KdtA * pz3, q4 = d4 * d4;
        float sd4 = d4 * fmaf(-0.16666667f, q4, 1.0f), cd4 = fmaf(-0.5f, q4, 1.0f);
        float By4 = fmaf(Bc, cd4, -Bs * sd4);
        float vx4 = px4 * A, vz4 = pz4 * A;
        float apx4 = pz4 * By4 * A, apz4 = -px4 * By4 * A;
        float dxs = h6 * (vx1 + 2.0f * (vx2 + vx3) + vx4);
        float dzs = h6 * (vz1 + 2.0f * (vz2 + vz3) + vz4);
        px = px + h6 * (apx1 + 2.0f * (apx2 + apx3) + apx4);
        pz = pz + h6 * (apz1 + 2.0f * (apz2 + apz3) + apz4);
        x += dxs; y += dt * vy; z += dzs;
        float dp = ku * dzs, qp = dp * dp;
        float sdp = dp * fmaf(-0.16666667f, qp, 1.0f), cdp = fmaf(-0.5f, qp, 1.0f);
        float cn = fmaf(cps, cdp, -sps * sdp);
        float sn = fmaf(sps, cdp, cps * sdp);
        float nr = fmaf(cn, cn, sn * sn);
        float corr = fmaf(-0.5f, nr, 1.5f);
        cps = cn * corr; sps = sn * corr;
        Bc = B0 * cps; Bs = B0 * sps;
        out[i] = x; out[Ns + i] = y; out[2 * Ns + i] = z;
        out[3 * Ns + i] = px * inv_cg; out[4 * Ns + i] = py * inv_cg; out[5 * Ns + i] = pz * inv_cg;
    }
}

extern "C" void kernel_launch(void* const* d_in, const int* in_sizes, int n_in,
                              void* d_out, int out_size) {
    const float* time = (const float*)d_in[0];
    const float* r0   = (const float*)d_in[1];
    const float* d0   = (const float*)d_in[2];
    const float* gam  = (const float*)d_in[3];
    const float* B0   = (const float*)d_in[4];
    const float* ku   = (const float*)d_in[5];
    float* out = (float*)d_out;
    int N = in_sizes[0];

    int G = (N + TILE - 1) / TILE;
    if (N > NMAXE || G > GMAX) {
        track_seq_kernel<<<1, 32>>>(time, r0, d0, gam, B0, ku, out, N);
        return;
    }
    const int L = 8;  // even: parity double-buffer returns to initial state
    for (int l = 0; l < L; ++l) {
        int mode = (l == 0) ? 0 : ((l == L - 1) ? 2 : 1);
        picard_kernel<<<G, TPB>>>(time, r0, d0, gam, B0, ku, out, N, mode, l & 1);
    }
}

// round 5
// speedup vs baseline: 289.9683x; 4.5529x over previous
#include <cuda_runtime.h>
#include <cuda_bf16.h>

// Single-launch persistent parallel-in-time undulator tracker.
// Physics: gamma,|p|,py invariant; (px,pz) = |pxz|*(sin,cos)(theta+phi0),
// theta = (B0 dt/g) cumtrapz cos(ku z); z/x/y ladders replicate the
// reference's f32 += quantization (q = ulp(ref)*rint(c/ulp)).
// Picard: init(ballistic) + 3 iterations + final, all in ONE kernel with
// grid barriers (grid=148 co-resident CTAs, 1/SM guaranteed by launch bounds).

#define TPB 512
#define GRD 148
#define EPT 14
#define CAP (TPB * GRD * EPT)
#define NSW 5

__device__ volatile unsigned g_gen;   // zero-initialized, monotonic across replays
__device__ unsigned g_cnt;
__device__ volatile float  g_totf[2][GRD];
__device__ volatile double g_totd[2][GRD];

static __device__ __forceinline__ float warp_iscan_f(float v, int lane) {
#pragma unroll
    for (int d = 1; d < 32; d <<= 1) {
        float n = __shfl_up_sync(0xffffffffu, v, d);
        if (lane >= d) v += n;
    }
    return v;
}
static __device__ __forceinline__ double warp_iscan_d(double v, int lane) {
#pragma unroll
    for (int d = 1; d < 32; d <<= 1) {
        double n = __shfl_up_sync(0xffffffffu, v, d);
        if (lane >= d) v += n;
    }
    return v;
}
static __device__ __forceinline__ float warp_sum_f(float v) {
#pragma unroll
    for (int d = 16; d; d >>= 1) v += __shfl_down_sync(0xffffffffu, v, d);
    return v;
}
static __device__ __forceinline__ double warp_sum_d(double v) {
#pragma unroll
    for (int d = 16; d; d >>= 1) v += __shfl_down_sync(0xffffffffu, v, d);
    return v;
}

static __device__ __forceinline__ void grid_barrier(unsigned target) {
    __syncthreads();
    if (threadIdx.x == 0) {
        __threadfence();
        unsigned prev = atomicAdd(&g_cnt, 1u);
        if (prev == GRD - 1) {
            g_cnt = 0;
            __threadfence();
            g_gen = target;
        } else {
            while (g_gen != target) { }
            __threadfence();
        }
    }
    __syncthreads();
}

// grid-wide exclusive prefix of per-thread totals (f32)
static __device__ float scan_grid_f(float tt, int sid, unsigned basegen,
                                    float* s_w, float* s_b) {
    int lane = threadIdx.x & 31, wid = threadIdx.x >> 5;
    float wi = warp_iscan_f(tt, lane);
    if (lane == 31) s_w[wid] = wi;
    __syncthreads();
    if (wid == 0) {
        float v = (lane < TPB / 32) ? s_w[lane] : 0.f;
        float sc = warp_iscan_f(v, lane);
        if (lane < TPB / 32) s_w[lane] = sc - v;
        float bt = __shfl_sync(0xffffffffu, sc, TPB / 32 - 1);
        if (lane == 0) g_totf[sid & 1][blockIdx.x] = bt;
    }
    grid_barrier(basegen + (unsigned)sid + 1u);
    if (wid == 0) {
        float acc = 0.f;
        for (int j = lane; j < GRD; j += 32)
            acc += (j < (int)blockIdx.x) ? g_totf[sid & 1][j] : 0.f;
        acc = warp_sum_f(acc);
        if (lane == 0) *s_b = acc;
    }
    __syncthreads();
    float res = *s_b + s_w[wid] + (wi - tt);
    __syncthreads();
    return res;
}

static __device__ double scan_grid_d(double tt, int sid, unsigned basegen,
                                     double* s_w, double* s_b) {
    int lane = threadIdx.x & 31, wid = threadIdx.x >> 5;
    double wi = warp_iscan_d(tt, lane);
    if (lane == 31) s_w[wid] = wi;
    __syncthreads();
    if (wid == 0) {
        double v = (lane < TPB / 32) ? s_w[lane] : 0.0;
        double sc = warp_iscan_d(v, lane);
        if (lane < TPB / 32) s_w[lane] = sc - v;
        double bt = __shfl_sync(0xffffffffu, sc, TPB / 32 - 1);
        if (lane == 0) g_totd[sid & 1][blockIdx.x] = bt;
    }
    grid_barrier(basegen + (unsigned)sid + 1u);
    if (wid == 0) {
        double acc = 0.0;
        for (int j = lane; j < GRD; j += 32)
            acc += (j < (int)blockIdx.x) ? g_totd[sid & 1][j] : 0.0;
        acc = warp_sum_d(acc);
        if (lane == 0) *s_b = acc;
    }
    __syncthreads();
    double res = *s_b + s_w[wid] + (wi - tt);
    __syncthreads();
    return res;
}

// f32-replicated field: psi = fl32(ku*z); 2-term Cody-Waite; fast cos.
static __device__ __forceinline__ float fval32(float kuf, float zf) {
    float psi = __fmul_rn(kuf, zf);
    float n = rintf(psi * 0.15915494309189535f);
    float r = fmaf(-n, 6.28125f, psi);                  // exact
    r = fmaf(-n, 1.9353071795864769e-3f, r);            // |err| <= ~3e-7
    return __cosf(r);
}

// fl32(ref + c) - ref, modeled as ulp(ref)-grid rounding of c.
static __device__ __forceinline__ double qstep(double c, double ref) {
    float rf = (float)ref;
    int e = (int)((__float_as_uint(rf) >> 23) & 0xffu);
    if (e == 0) return c;
    double u  = __longlong_as_double((long long)(e - 150 + 1023) << 52);
    double iu = __longlong_as_double((long long)(150 - e + 1023) << 52);
    return u * rint(c * iu);
}

__global__ void __launch_bounds__(TPB, 1) picard_all(
    const float* __restrict__ time, const float* __restrict__ r0v,
    const float* __restrict__ d0v, const float* __restrict__ gptr,
    const float* __restrict__ b0ptr, const float* __restrict__ kuptr,
    float* __restrict__ out, int N)
{
    __shared__ float  s_wf[TPB / 32];
    __shared__ double s_wd[TPB / 32];
    __shared__ float  s_bf;
    __shared__ double s_bd;
    __shared__ unsigned s_base;

    const int tid = threadIdx.x;
    if (tid == 0) s_base = g_gen;
    __syncthreads();
    const unsigned basegen = s_base;

    // scalars (f32-replicated initial momentum)
    const double Cc = 0.29979245;
    const double dt = (double)(time[1] - time[0]);
    const double gamma = (double)gptr[0];
    const double B0 = (double)b0ptr[0];
    const float kuf = kuptr[0];
    float dxf = d0v[0], dyf = d0v[1], dzf = d0v[2];
    float gf = gptr[0];
    float dnf = sqrtf(dxf * dxf + dyf * dyf + dzf * dzf);
    float csf = 0.29979245f * sqrtf(gf * gf - 1.0f);
    const double px0 = (double)(csf * dxf / dnf);
    const double py0 = (double)(csf * dyf / dnf);
    const double pz0 = (double)(csf * dzf / dnf);
    const double x0 = (double)r0v[0], y0 = (double)r0v[1], z0 = (double)r0v[2];
    const double invg = 1.0 / gamma;
    const float Kthf = (float)(B0 * dt * invg);
    const double invcg = 1.0 / (Cc * gamma);
    const double vzdt = pz0 * invg * dt;
    const float f0f = fval32(kuf, (float)z0);
    const double cy = dt * py0 * invg;
    const double Pmag = sqrt(px0 * px0 + pz0 * pz0);
    const double phi0 = atan2(px0, pz0);
    const double Kz = dt * invg * Pmag;

    const int base = ((int)blockIdx.x * TPB + tid) * EPT;

    double z[EPT];
    float fs[EPT], qs[EPT];
    int sid = 0;

    // ---- init + Picard iterations ----
    for (int sw = 0; sw < NSW - 1; ++sw) {
        float Tf = 0.f;
#pragma unroll
        for (int k = 0; k < EPT; ++k) {
            int i = base + k;
            if (sw == 0) z[k] = z0 + vzdt * (double)i;
            float f = (i < N) ? fval32(kuf, (float)z[k]) : 0.f;
            fs[k] = f; Tf += f;
        }
        float exf = scan_grid_f(Tf, sid++, basegen, s_wf, &s_bf);

        double Tq = 0.0; float run = exf;
#pragma unroll
        for (int k = 0; k < EPT; ++k) {
            int i = base + k;
            run += fs[k];
            float th = Kthf * (run - 0.5f * (f0f + fs[k]));
            float thm = fmaf(0.5f * Kthf, fs[k], th);
            double u = phi0 + (double)thm;
            double u2 = u * u;
            double cu = fma(u2, fma(u2, 1.0 / 24.0, -0.5), 1.0);
            double cz = Kz * cu;
            float qf = (i < N) ? (float)qstep(cz, z[k]) : 0.f;
            qs[k] = qf;
            Tq += (double)qf;
        }
        double exq = scan_grid_d(Tq, sid++, basegen, s_wd, &s_bd);

        double runq = exq;
#pragma unroll
        for (int k = 0; k < EPT; ++k) {
            z[k] = z0 + runq;          // exclusive prefix -> z_i
            runq += (double)qs[k];
        }
    }

    // ---- final sweep ----
    float Tf = 0.f;
#pragma unroll
    for (int k = 0; k < EPT; ++k) {
        int i = base + k;
        float f = (i < N) ? fval32(kuf, (float)z[k]) : 0.f;
        fs[k] = f; Tf += f;
    }
    float exf = scan_grid_f(Tf, sid++, basegen, s_wf, &s_bf);

    float cxs[EPT];
    double Tq = 0.0; float Tcx = 0.f; float run = exf;
#pragma unroll
    for (int k = 0; k < EPT; ++k) {
        int i = base + k;
        run += fs[k];
        float th = Kthf * (run - 0.5f * (f0f + fs[k]));
        float thm = fmaf(0.5f * Kthf, fs[k], th);
        double u = phi0 + (double)thm;
        double u2 = u * u;
        double cu = fma(u2, fma(u2, 1.0 / 24.0, -0.5), 1.0);
        double su = u * fma(u2, fma(u2, 1.0 / 120.0, -1.0 / 6.0), 1.0);
        double cz = Kz * cu;
        double cx = Kz * su;
        float qf = (i < N) ? (float)qstep(cz, z[k]) : 0.f;
        qs[k] = qf;  Tq += (double)qf;
        float cxf = (i < N) ? (float)cx : 0.f;
        cxs[k] = cxf;  Tcx += cxf;
        fs[k] = th;                    // keep node theta for outputs
    }
    double exq = scan_grid_d(Tq, sid++, basegen, s_wd, &s_bd);
    float excx = scan_grid_f(Tcx, sid++, basegen, s_wf, &s_bf);

    // z ladder (output) + quantized-x increments (binade from plain x)
    double Tqx = 0.0;
    double runq = exq; float runcx = excx;
#pragma unroll
    for (int k = 0; k < EPT; ++k) {
        int i = base + k;
        z[k] = z0 + runq;
        runq += (double)qs[k];
        double xplain = x0 + (double)runcx;          // exclusive plain x_i
        float qxf = (i < N) ? (float)qstep((double)cxs[k], xplain) : 0.f;
        runcx += cxs[k];
        cxs[k] = qxf;  Tqx += (double)qxf;
    }
    double exqx = scan_grid_d(Tqx, sid++, basegen, s_wd, &s_bd);

    // y ladder (constant increment, closed-form plain value)
    double Tqy = 0.0;
#pragma unroll
    for (int k = 0; k < EPT; ++k) {
        int i = base + k;
        double ypl = y0 + cy * (double)i;
        float qyf = (i < N) ? (float)qstep(cy, ypl) : 0.f;
        qs[k] = qyf;  Tqy += (double)qyf;
    }
    double exqy = scan_grid_d(Tqy, sid++, basegen, s_wd, &s_bd);

    // ---- outputs ----
    size_t Ns = (size_t)N;
    double runqx = exqx, runqy = exqy;
#pragma unroll
    for (int k = 0; k < EPT; ++k) {
        int i = base + k;
        double xh = x0 + runqx; runqx += (double)cxs[k];
        double yh = y0 + runqy; runqy += (double)qs[k];
        if (i < N) {
            double u = phi0 + (double)fs[k];
            double u2 = u * u;
            double cu = fma(u2, fma(u2, 1.0 / 24.0, -0.5), 1.0);
            double su = u * fma(u2, fma(u2, 1.0 / 120.0, -1.0 / 6.0), 1.0);
            double px = Pmag * su, pz = Pmag * cu;
            out[i]          = (float)xh;
            out[Ns + i]     = (float)yh;
            out[2 * Ns + i] = (float)z[k];
            out[3 * Ns + i] = (float)(px * invcg);
            out[4 * Ns + i] = (float)(py0 * invcg);
            out[5 * Ns + i] = (float)(pz * invcg);
        }
    }
}

// ---------------- serial fallback (N exceeds capacity) ---------------------
__global__ void __launch_bounds__(32, 1) track_seq_kernel(
    const float* __restrict__ time, const float* __restrict__ r0v,
    const float* __restrict__ d0v, const float* __restrict__ gptr,
    const float* __restrict__ b0ptr, const float* __restrict__ kuptr,
    float* __restrict__ out, int N)
{
    if (threadIdx.x != 0 || blockIdx.x != 0) return;
    const float C = 0.29979245f;
    const float dt = time[1] - time[0];
    const float dt2 = 0.5f * dt, h6 = dt * (1.0f / 6.0f);
    const float gamma = gptr[0], B0 = b0ptr[0], ku = kuptr[0];
    const float A = 1.0f / gamma;
    const float KdtA2 = ku * dt2 * A, KdtA = ku * dt * A;
    const float inv_cg = 1.0f / (C * gamma);
    float dx0 = d0v[0], dy0 = d0v[1], dz0 = d0v[2];
    float dn = sqrtf(dx0 * dx0 + dy0 * dy0 + dz0 * dz0);
    float pscale = C * sqrtf(gamma * gamma - 1.0f) / dn;
    float px = pscale * dx0, py = pscale * dy0, pz = pscale * dz0;
    float x = r0v[0], y = r0v[1], z = r0v[2];
    const float vy = py * A;
    float cps = cosf(ku * z), sps = sinf(ku * z);
    float Bc = B0 * cps, Bs = B0 * sps;
    const size_t Ns = (size_t)N;
    out[0] = x; out[Ns] = y; out[2 * Ns] = z;
    out[3 * Ns] = px * inv_cg; out[4 * Ns] = py * inv_cg; out[5 * Ns] = pz * inv_cg;
#pragma unroll 1
    for (int i = 1; i < N; ++i) {
        float vx1 = px * A, vz1 = pz * A;
        float apx1 = pz * Bc * A, apz1 = -px * Bc * A;
        float px2 = fmaf(apx1, dt2, px), pz2 = fmaf(apz1, dt2, pz);
        float d2 = KdtA2 * pz, q2 = d2 * d2;
        float sd2 = d2 * fmaf(-0.16666667f, q2, 1.0f), cd2 = fmaf(-0.5f, q2, 1.0f);
        float By2 = fmaf(Bc, cd2, -Bs * sd2);
        float vx2 = px2 * A, vz2 = pz2 * A;
        float apx2 = pz2 * By2 * A, apz2 = -px2 * By2 * A;
        float px3 = fmaf(apx2, dt2, px), pz3 = fmaf(apz2, dt2, pz);
        float d3 = KdtA2 * pz2, q3 = d3 * d3;
        float sd3 = d3 * fmaf(-0.16666667f, q3, 1.0f), cd3 = fmaf(-0.5f, q3, 1.0f);
        float By3 = fmaf(Bc, cd3, -Bs * sd3);
        float vx3 = px3 * A, vz3 = pz3 * A;
        float apx3 = pz3 * By3 * A, apz3 = -px3 * By3 * A;
        float px4 = fmaf(apx3, dt, px), pz4 = fmaf(apz3, dt, pz);
        float d4 = KdtA * pz3, q4 = d4 * d4;
        float sd4 = d4 * fmaf(-0.16666667f, q4, 1.0f), cd4 = fmaf(-0.5f, q4, 1.0f);
        float By4 = fmaf(Bc, cd4, -Bs * sd4);
        float vx4 = px4 * A, vz4 = pz4 * A;
        float apx4 = pz4 * By4 * A, apz4 = -px4 * By4 * A;
        float dxs = h6 * (vx1 + 2.0f * (vx2 + vx3) + vx4);
        float dzs = h6 * (vz1 + 2.0f * (vz2 + vz3) + vz4);
        px = px + h6 * (apx1 + 2.0f * (apx2 + apx3) + apx4);
        pz = pz + h6 * (apz1 + 2.0f * (apz2 + apz3) + apz4);
        x += dxs; y += dt * vy; z += dzs;
        float dp = ku * dzs, qp = dp * dp;
        float sdp = dp * fmaf(-0.16666667f, qp, 1.0f), cdp = fmaf(-0.5f, qp, 1.0f);
        float cn = fmaf(cps, cdp, -sps * sdp);
        float sn = fmaf(sps, cdp, cps * sdp);
        float nr = fmaf(cn, cn, sn * sn);
        float corr = fmaf(-0.5f, nr, 1.5f);
        cps = cn * corr; sps = sn * corr;
        Bc = B0 * cps; Bs = B0 * sps;
        out[i] = x; out[Ns + i] = y; out[2 * Ns + i] = z;
        out[3 * Ns + i] = px * inv_cg; out[4 * Ns + i] = py * inv_cg; out[5 * Ns + i] = pz * inv_cg;
    }
}

extern "C" void kernel_launch(void* const* d_in, const int* in_sizes, int n_in,
                              void* d_out, int out_size) {
    const float* time = (const float*)d_in[0];
    const float* r0   = (const float*)d_in[1];
    const float* d0   = (const float*)d_in[2];
    const float* gam  = (const float*)d_in[3];
    const float* B0   = (const float*)d_in[4];
    const float* ku   = (const float*)d_in[5];
    float* out = (float*)d_out;
    int N = in_sizes[0];

    if (N > CAP) {
        track_seq_kernel<<<1, 32>>>(time, r0, d0, gam, B0, ku, out, N);
        return;
    }
    picard_all<<<GRD, TPB>>>(time, r0, d0, gam, B0, ku, out, N);
}

// round 7
// speedup vs baseline: 672.3395x; 2.3187x over previous
#include <cuda_runtime.h>
#include <cuda_bf16.h>

// Single-launch persistent parallel-in-time undulator tracker (f32 compute,
// f64 only in ladder prefix sums).
// Physics: gamma,|p|,py invariant; (px,pz) = |pxz|*(sin,cos)(phi0+theta),
// theta = (B0 dt/g) cumtrapz cos(ku z). z/x/y ladders replicate the
// reference's f32 "+=" quantization: q = ulp(ref)*rint(c/ulp(ref)).
// Picard: ballistic init + 2 iterations + final, one kernel, 9 grid barriers.

#define TPB 512
#define GRD 148
#define EPT 14
#define TILE (TPB * EPT)
#define CAP (TILE * GRD)
#define NPRE 3              // pre-final sweeps (incl. ballistic init)

__device__ volatile unsigned g_gen;     // monotonic across graph replays
__device__ unsigned g_cnt;
__device__ volatile float  g_totf[2][GRD];
__device__ volatile double g_totd[2][GRD];
__device__ volatile double g_totd2[2][GRD];

struct SMem {
    float  wf[TPB / 32];
    double wd[TPB / 32];
    double wd2[TPB / 32];
    float  bf;
    double bd, bd2;
    unsigned base;
    float stage[TILE];      // 28 KB output-transpose buffer
};

static __device__ __forceinline__ float warp_iscan_f(float v, int lane) {
#pragma unroll
    for (int d = 1; d < 32; d <<= 1) {
        float n = __shfl_up_sync(0xffffffffu, v, d);
        if (lane >= d) v += n;
    }
    return v;
}
static __device__ __forceinline__ double warp_iscan_d(double v, int lane) {
#pragma unroll
    for (int d = 1; d < 32; d <<= 1) {
        double n = __shfl_up_sync(0xffffffffu, v, d);
        if (lane >= d) v += n;
    }
    return v;
}
static __device__ __forceinline__ float warp_sum_f(float v) {
#pragma unroll
    for (int d = 16; d; d >>= 1) v += __shfl_down_sync(0xffffffffu, v, d);
    return v;
}
static __device__ __forceinline__ double warp_sum_d(double v) {
#pragma unroll
    for (int d = 16; d; d >>= 1) v += __shfl_down_sync(0xffffffffu, v, d);
    return v;
}

static __device__ __forceinline__ void grid_barrier(unsigned target) {
    __syncthreads();
    if (threadIdx.x == 0) {
        __threadfence();
        unsigned prev = atomicAdd(&g_cnt, 1u);
        if (prev == GRD - 1) {
            g_cnt = 0;
            __threadfence();
            g_gen = target;
        } else {
            while (g_gen != target) { }
            __threadfence();
        }
    }
    __syncthreads();
}

// Fused grid-exclusive-prefix of (float a, double b) totals. One barrier.
static __device__ void scan_fd(SMem* sm, float tf, double td, int sid,
                               unsigned bg, float& exf, double& exd) {
    const int lane = threadIdx.x & 31, wid = threadIdx.x >> 5;
    const int buf = sid & 1;
    __syncthreads();
    float wf = warp_iscan_f(tf, lane);
    double wd = warp_iscan_d(td, lane);
    if (lane == 31) { sm->wf[wid] = wf; sm->wd[wid] = wd; }
    __syncthreads();
    if (wid == 0) {
        const int nw = TPB / 32;
        float vf = (lane < nw) ? sm->wf[lane] : 0.f;
        double vd = (lane < nw) ? sm->wd[lane] : 0.0;
        float sf = warp_iscan_f(vf, lane);
        double sd = warp_iscan_d(vd, lane);
        if (lane < nw) { sm->wf[lane] = sf - vf; sm->wd[lane] = sd - vd; }
        if (lane == nw - 1) {
            g_totf[buf][blockIdx.x] = sf;
            g_totd[buf][blockIdx.x] = sd;
        }
    }
    grid_barrier(bg + (unsigned)sid + 1u);
    if (wid == 0) {
        float af = 0.f; double ad = 0.0;
        for (int j = lane; j < GRD; j += 32) {
            if (j < (int)blockIdx.x) { af += g_totf[buf][j]; ad += g_totd[buf][j]; }
        }
        af = warp_sum_f(af); ad = warp_sum_d(ad);
        if (lane == 0) { sm->bf = af; sm->bd = ad; }
    }
    __syncthreads();
    exf = sm->bf + sm->wf[wid] + (wf - tf);
    exd = sm->bd + sm->wd[wid] + (wd - td);
}

// Fused grid-exclusive-prefix of (double a, double b). One barrier.
static __device__ void scan_dd(SMem* sm, double ta, double tb, int sid,
                               unsigned bg, double& exa, double& exb) {
    const int lane = threadIdx.x & 31, wid = threadIdx.x >> 5;
    const int buf = sid & 1;
    __syncthreads();
    double wa = warp_iscan_d(ta, lane);
    double wb = warp_iscan_d(tb, lane);
    if (lane == 31) { sm->wd[wid] = wa; sm->wd2[wid] = wb; }
    __syncthreads();
    if (wid == 0) {
        const int nw = TPB / 32;
        double va = (lane < nw) ? sm->wd[lane] : 0.0;
        double vb = (lane < nw) ? sm->wd2[lane] : 0.0;
        double sa = warp_iscan_d(va, lane);
        double sb = warp_iscan_d(vb, lane);
        if (lane < nw) { sm->wd[lane] = sa - va; sm->wd2[lane] = sb - vb; }
        if (lane == nw - 1) {
            g_totd[buf][blockIdx.x] = sa;
            g_totd2[buf][blockIdx.x] = sb;
        }
    }
    grid_barrier(bg + (unsigned)sid + 1u);
    if (wid == 0) {
        double aa = 0.0, ab = 0.0;
        for (int j = lane; j < GRD; j += 32) {
            if (j < (int)blockIdx.x) { aa += g_totd[buf][j]; ab += g_totd2[buf][j]; }
        }
        aa = warp_sum_d(aa); ab = warp_sum_d(ab);
        if (lane == 0) { sm->bd = aa; sm->bd2 = ab; }
    }
    __syncthreads();
    exa = sm->bd + sm->wd[wid] + (wa - ta);
    exb = sm->bd2 + sm->wd2[wid] + (wb - tb);
}

// f32-replicated field: psi = fl32(ku*z) (exactly the ref's product);
// 2-term Cody-Waite reduction (n<=1001 exact), fast cos.
static __device__ __forceinline__ float fval32(float kuf, float zf) {
    float psi = __fmul_rn(kuf, zf);
    float n = rintf(psi * 0.15915494309189535f);
    float r = fmaf(-n, 6.28125f, psi);
    r = fmaf(-n, 1.9353071795864769e-3f, r);
    return __cosf(r);
}

// fl32(ref + c) - ref modeled as ulp(ref)-grid rounding of c (all f32).
static __device__ __forceinline__ float qstepf(float c, float ref) {
    int e = (int)((__float_as_uint(fabsf(ref)) >> 23) & 0xffu);
    if (e < 24) return c;                       // |ref| tiny: grid below c's eps
    float u  = __uint_as_float((unsigned)(e - 23) << 23);   // 2^(e-150)
    float iu = __uint_as_float((unsigned)(277 - e) << 23);  // 2^(150-e)
    return u * rintf(c * iu);
}

__global__ void __launch_bounds__(TPB, 1) picard_all(
    const float* __restrict__ time, const float* __restrict__ r0v,
    const float* __restrict__ d0v, const float* __restrict__ gptr,
    const float* __restrict__ b0ptr, const float* __restrict__ kuptr,
    float* __restrict__ out, int N)
{
    __shared__ SMem sm;
    const int tid = threadIdx.x;
    if (tid == 0) sm.base = g_gen;
    __syncthreads();
    const unsigned bg = sm.base;

    // ---- scalars (f32-replicated initial momentum) ----
    const double dt = (double)(time[1] - time[0]);
    const double gamma = (double)gptr[0];
    const double B0 = (double)b0ptr[0];
    const float kuf = kuptr[0];
    float dxf = d0v[0], dyf = d0v[1], dzf = d0v[2];
    float gf = gptr[0];
    float dnf = sqrtf(dxf * dxf + dyf * dyf + dzf * dzf);
    float csf = 0.29979245f * sqrtf(gf * gf - 1.0f);
    const double px0 = (double)(csf * dxf / dnf);
    const double py0 = (double)(csf * dyf / dnf);
    const double pz0 = (double)(csf * dzf / dnf);
    const double x0 = (double)r0v[0], y0 = (double)r0v[1], z0 = (double)r0v[2];
    const double invg = 1.0 / gamma;
    const double Pmag = sqrt(px0 * px0 + pz0 * pz0);
    const float Kthf  = (float)(B0 * dt * invg);
    const float Kzf   = (float)(dt * invg * Pmag);
    const float phi0f = (float)atan2(px0, pz0);
    const float f0f   = fval32(kuf, (float)z0);
    const double cy   = dt * py0 * invg;
    const float cyf   = (float)cy;
    const double vzdt = pz0 * invg * dt;
    const float scalef = (float)(Pmag / (0.29979245 * gamma));  // |p_xz|/(C*gamma)
    const float byc    = (float)(py0 / (0.29979245 * gamma));

    const int base = ((int)blockIdx.x * TPB + tid) * EPT;
    const int blk0 = (int)blockIdx.x * TILE;

    float zf[EPT], fs[EPT], qs[EPT], cxs[EPT];
    int sid = 0;
    float dumf; double dumd;

    // ---- pre-final sweeps: ballistic init + Picard iterations ----
    for (int sw = 0; sw < NPRE; ++sw) {
        float Tf = 0.f;
#pragma unroll
        for (int k = 0; k < EPT; ++k) {
            int i = base + k;
            if (sw == 0) zf[k] = (float)(z0 + vzdt * (double)i);
            float f = (i < N) ? fval32(kuf, zf[k]) : 0.f;
            fs[k] = f; Tf += f;
        }
        float exf;
        scan_fd(&sm, Tf, 0.0, sid, bg, exf, dumd); sid++;

        double Tq = 0.0; float run = exf;
#pragma unroll
        for (int k = 0; k < EPT; ++k) {
            int i = base + k;
            run += fs[k];
            float th  = Kthf * (run - 0.5f * (f0f + fs[k]));
            float thm = fmaf(0.5f * Kthf, fs[k], th);
            float u = phi0f + thm;
            float u2 = u * u;
            float cu = fmaf(u2, fmaf(u2, 1.f / 24.f, -0.5f), 1.f);
            float cz = Kzf * cu;
            float qf = (i < N) ? qstepf(cz, zf[k]) : 0.f;
            qs[k] = qf;
            Tq += (double)qf;
        }
        double exq;
        scan_fd(&sm, 0.f, Tq, sid, bg, dumf, exq); sid++;

        double runq = exq;
#pragma unroll
        for (int k = 0; k < EPT; ++k) {
            zf[k] = (float)(z0 + runq);      // exclusive prefix -> z_i
            runq += (double)qs[k];
        }
    }

    // ---- final sweep ----
    float Tf = 0.f;
#pragma unroll
    for (int k = 0; k < EPT; ++k) {
        int i = base + k;
        float f = (i < N) ? fval32(kuf, zf[k]) : 0.f;
        fs[k] = f; Tf += f;
    }
    float exf;
    scan_fd(&sm, Tf, 0.0, sid, bg, exf, dumd); sid++;

    double Tq = 0.0; float Tcx = 0.f; float run = exf;
#pragma unroll
    for (int k = 0; k < EPT; ++k) {
        int i = base + k;
        run += fs[k];
        float th  = Kthf * (run - 0.5f * (f0f + fs[k]));
        float thm = fmaf(0.5f * Kthf, fs[k], th);
        float u = phi0f + thm;
        float u2 = u * u;
        float cu = fmaf(u2, fmaf(u2, 1.f / 24.f, -0.5f), 1.f);
        float su = u * fmaf(u2, fmaf(u2, 1.f / 120.f, -1.f / 6.f), 1.f);
        float cz = Kzf * cu;
        float cx = (i < N) ? Kzf * su : 0.f;
        float qf = (i < N) ? qstepf(cz, zf[k]) : 0.f;
        qs[k] = qf;   Tq += (double)qf;
        cxs[k] = cx;  Tcx += cx;
        fs[k] = th;                           // keep node theta
    }
    float excx; double exq;
    scan_fd(&sm, Tcx, Tq, sid, bg, excx, exq); sid++;

    double Tqx = 0.0, Tqy = 0.0;
    {
        double runq = exq; float runcx = excx;
#pragma unroll
        for (int k = 0; k < EPT; ++k) {
            int i = base + k;
            float zi = (float)(z0 + runq);    // quantized-ladder z output
            runq += (double)qs[k];
            zf[k] = zi;
            float xpl = (float)(x0 + (double)runcx);   // plain x_i (binade ref)
            float qx = (i < N) ? qstepf(cxs[k], xpl) : 0.f;
            runcx += cxs[k];
            cxs[k] = qx;  Tqx += (double)qx;
            float ypl = (float)(y0 + cy * (double)i);
            float qy = (i < N) ? qstepf(cyf, ypl) : 0.f;
            qs[k] = qy;   Tqy += (double)qy;
        }
    }
    double exqx, exqy;
    scan_dd(&sm, Tqx, Tqy, sid, bg, exqx, exqy); sid++;

    // ---- outputs: compute into smem stage (thread-contiguous), write coalesced
    const size_t Ns = (size_t)N;
    const int nrem = N - blk0;                 // elements this block owns (may exceed TILE)

    // x
    {
        double runqx = exqx;
        __syncthreads();
#pragma unroll
        for (int k = 0; k < EPT; ++k) {
            sm.stage[tid * EPT + k] = (float)(x0 + runqx);
            runqx += (double)cxs[k];
        }
        __syncthreads();
        for (int j = tid; j < TILE; j += TPB)
            if (j < nrem) out[blk0 + j] = sm.stage[j];
    }
    // y
    {
        double runqy = exqy;
        __syncthreads();
#pragma unroll
        for (int k = 0; k < EPT; ++k) {
            sm.stage[tid * EPT + k] = (float)(y0 + runqy);
            runqy += (double)qs[k];
        }
        __syncthreads();
        for (int j = tid; j < TILE; j += TPB)
            if (j < nrem) out[Ns + blk0 + j] = sm.stage[j];
    }
    // z
    {
        __syncthreads();
#pragma unroll
        for (int k = 0; k < EPT; ++k)
            sm.stage[tid * EPT + k] = zf[k];
        __syncthreads();
        for (int j = tid; j < TILE; j += TPB)
            if (j < nrem) out[2 * Ns + blk0 + j] = sm.stage[j];
    }
    // beta_x
    {
        __syncthreads();
#pragma unroll
        for (int k = 0; k < EPT; ++k) {
            float u = phi0f + fs[k];
            float u2 = u * u;
            float su = u * fmaf(u2, fmaf(u2, 1.f / 120.f, -1.f / 6.f), 1.f);
            sm.stage[tid * EPT + k] = scalef * su;
        }
        __syncthreads();
        for (int j = tid; j < TILE; j += TPB)
            if (j < nrem) out[3 * Ns + blk0 + j] = sm.stage[j];
    }
    // beta_y (constant)
    for (int j = tid; j < TILE; j += TPB)
        if (j < nrem) out[4 * Ns + blk0 + j] = byc;
    // beta_z
    {
        __syncthreads();
#pragma unroll
        for (int k = 0; k < EPT; ++k) {
            float u = phi0f + fs[k];
            float u2 = u * u;
            float cu = fmaf(u2, fmaf(u2, 1.f / 24.f, -0.5f), 1.f);
            sm.stage[tid * EPT + k] = scalef * cu;
        }
        __syncthreads();
        for (int j = tid; j < TILE; j += TPB)
            if (j < nrem) out[5 * Ns + blk0 + j] = sm.stage[j];
    }
}

// ---------------- serial fallback (N exceeds capacity) ---------------------
__global__ void __launch_bounds__(32, 1) track_seq_kernel(
    const float* __restrict__ time, const float* __restrict__ r0v,
    const float* __restrict__ d0v, const float* __restrict__ gptr,
    const float* __restrict__ b0ptr, const float* __restrict__ kuptr,
    float* __restrict__ out, int N)
{
    if (threadIdx.x != 0 || blockIdx.x != 0) return;
    const float C = 0.29979245f;
    const float dt = time[1] - time[0];
    const float dt2 = 0.5f * dt, h6 = dt * (1.0f / 6.0f);
    const float gamma = gptr[0], B0 = b0ptr[0], ku = kuptr[0];
    const float A = 1.0f / gamma;
    const float KdtA2 = ku * dt2 * A, KdtA = ku * dt * A;
    const float inv_cg = 1.0f / (C * gamma);
    float dx0 = d0v[0], dy0 = d0v[1], dz0 = d0v[2];
    float dn = sqrtf(dx0 * dx0 + dy0 * dy0 + dz0 * dz0);
    float pscale = C * sqrtf(gamma * gamma - 1.0f) / dn;
    float px = pscale * dx0, py = pscale * dy0, pz = pscale * dz0;
    float x = r0v[0], y = r0v[1], z = r0v[2];
    const float vy = py * A;
    float cps = cosf(ku * z), sps = sinf(ku * z);
    float Bc = B0 * cps, Bs = B0 * sps;
    const size_t Ns = (size_t)N;
    out[0] = x; out[Ns] = y; out[2 * Ns] = z;
    out[3 * Ns] = px * inv_cg; out[4 * Ns] = py * inv_cg; out[5 * Ns] = pz * inv_cg;
#pragma unroll 1
    for (int i = 1; i < N; ++i) {
        float vx1 = px * A, vz1 = pz * A;
        float apx1 = pz * Bc * A, apz1 = -px * Bc * A;
        float px2 = fmaf(apx1, dt2, px), pz2 = fmaf(apz1, dt2, pz);
        float d2 = KdtA2 * pz, q2 = d2 * d2;
        float sd2 = d2 * fmaf(-0.16666667f, q2, 1.0f), cd2 = fmaf(-0.5f, q2, 1.0f);
        float By2 = fmaf(Bc, cd2, -Bs * sd2);
        float vx2 = px2 * A, vz2 = pz2 * A;
        float apx2 = pz2 * By2 * A, apz2 = -px2 * By2 * A;
        float px3 = fmaf(apx2, dt2, px), pz3 = fmaf(apz2, dt2, pz);
        float d3 = KdtA2 * pz2, q3 = d3 * d3;
        float sd3 = d3 * fmaf(-0.16666667f, q3, 1.0f), cd3 = fmaf(-0.5f, q3, 1.0f);
        float By3 = fmaf(Bc, cd3, -Bs * sd3);
        float vx3 = px3 * A, vz3 = pz3 * A;
        float apx3 = pz3 * By3 * A, apz3 = -px3 * By3 * A;
        float px4 = fmaf(apx3, dt, px), pz4 = fmaf(apz3, dt, pz);
        float d4 = KdtA * pz3, q4 = d4 * d4;
        float sd4 = d4 * fmaf(-0.16666667f, q4, 1.0f), cd4 = fmaf(-0.5f, q4, 1.0f);
        float By4 = fmaf(Bc, cd4, -Bs * sd4);
        float vx4 = px4 * A, vz4 = pz4 * A;
        float apx4 = pz4 * By4 * A, apz4 = -px4 * By4 * A;
        float dxs = h6 * (vx1 + 2.0f * (vx2 + vx3) + vx4);
        float dzs = h6 * (vz1 + 2.0f * (vz2 + vz3) + vz4);
        px = px + h6 * (apx1 + 2.0f * (apx2 + apx3) + apx4);
        pz = pz + h6 * (apz1 + 2.0f * (apz2 + apz3) + apz4);
        x += dxs; y += dt * vy; z += dzs;
        float dp = ku * dzs, qp = dp * dp;
        float sdp = dp * fmaf(-0.16666667f, qp, 1.0f), cdp = fmaf(-0.5f, qp, 1.0f);
        float cn = fmaf(cps, cdp, -sps * sdp);
        float sn = fmaf(sps, cdp, cps * sdp);
        float nr = fmaf(cn, cn, sn * sn);
        float corr = fmaf(-0.5f, nr, 1.5f);
        cps = cn * corr; sps = sn * corr;
        Bc = B0 * cps; Bs = B0 * sps;
        out[i] = x; out[Ns + i] = y; out[2 * Ns + i] = z;
        out[3 * Ns + i] = px * inv_cg; out[4 * Ns + i] = py * inv_cg; out[5 * Ns + i] = pz * inv_cg;
    }
}

extern "C" void kernel_launch(void* const* d_in, const int* in_sizes, int n_in,
                              void* d_out, int out_size) {
    const float* time = (const float*)d_in[0];
    const float* r0   = (const float*)d_in[1];
    const float* d0   = (const float*)d_in[2];
    const float* gam  = (const float*)d_in[3];
    const float* B0   = (const float*)d_in[4];
    const float* ku   = (const float*)d_in[5];
    float* out = (float*)d_out;
    int N = in_sizes[0];

    if (N > CAP) {
        track_seq_kernel<<<1, 32>>>(time, r0, d0, gam, B0, ku, out, N);
        return;
    }
    picard_all<<<GRD, TPB>>>(time, r0, d0, gam, B0, ku, out, N);
}

// round 8
// speedup vs baseline: 712.2754x; 1.0594x over previous
#include <cuda_runtime.h>
#include <cuda_bf16.h>

// Persistent single-launch parallel-in-time undulator tracker.
// f32 compute with exact-grid f32 local ladders; f64 only in the scan
// network + per-element independent base adds. 2 pre-sweeps (analytic
// secular-corrected ballistic init + 1 Picard) + final. 7 grid barriers.

#define TPB 1024
#define GRD 148
#define EPT 7
#define TILE (TPB * EPT)          // 7168
#define CAP (TILE * GRD)          // 1,060,864
#define NPRE 2

__device__ volatile unsigned g_gen;   // monotonic across graph replays
__device__ unsigned g_cnt;
__device__ volatile float  g_totf[2][GRD];
__device__ volatile double g_totd[2][GRD];
__device__ volatile double g_totd2[2][GRD];

struct SMem {
    float  wf[32];
    double wd[32];
    double wd2[32];
    float  bf;
    double bd, bd2;
    unsigned base;
    float stage[TILE];            // 28 KB output transpose buffer
};

static __device__ __forceinline__ float warp_iscan_f(float v, int lane) {
#pragma unroll
    for (int d = 1; d < 32; d <<= 1) {
        float n = __shfl_up_sync(0xffffffffu, v, d);
        if (lane >= d) v += n;
    }
    return v;
}
static __device__ __forceinline__ double warp_iscan_d(double v, int lane) {
#pragma unroll
    for (int d = 1; d < 32; d <<= 1) {
        double n = __shfl_up_sync(0xffffffffu, v, d);
        if (lane >= d) v += n;
    }
    return v;
}
static __device__ __forceinline__ float warp_sum_f(float v) {
#pragma unroll
    for (int d = 16; d; d >>= 1) v += __shfl_down_sync(0xffffffffu, v, d);
    return v;
}
static __device__ __forceinline__ double warp_sum_d(double v) {
#pragma unroll
    for (int d = 16; d; d >>= 1) v += __shfl_down_sync(0xffffffffu, v, d);
    return v;
}

static __device__ __forceinline__ void grid_barrier(unsigned target) {
    __syncthreads();
    if (threadIdx.x == 0) {
        __threadfence();
        unsigned prev = atomicAdd(&g_cnt, 1u);
        if (prev == GRD - 1) {
            g_cnt = 0;
            __threadfence();
            g_gen = target;
        } else {
            while (g_gen != target) { }
            __threadfence();
        }
    }
    __syncthreads();
}

// ---- grid exclusive-prefix scans (sid selects double-buffer parity) ----
static __device__ float scan_f(SMem* sm, float tf, int sid, unsigned bg) {
    const int lane = threadIdx.x & 31, wid = threadIdx.x >> 5;
    const int buf = sid & 1;
    __syncthreads();
    float wf = warp_iscan_f(tf, lane);
    if (lane == 31) sm->wf[wid] = wf;
    __syncthreads();
    if (wid == 0) {
        float vf = sm->wf[lane];
        float sf = warp_iscan_f(vf, lane);
        sm->wf[lane] = sf - vf;
        if (lane == 31) g_totf[buf][blockIdx.x] = sf;
    }
    grid_barrier(bg + (unsigned)sid + 1u);
    if (wid == 0) {
        float af = 0.f;
#pragma unroll
        for (int j = lane; j < GRD; j += 32)
            if (j < (int)blockIdx.x) af += g_totf[buf][j];
        af = warp_sum_f(af);
        if (lane == 0) sm->bf = af;
    }
    __syncthreads();
    return sm->bf + sm->wf[wid] + (wf - tf);
}

static __device__ double scan_d(SMem* sm, double td, int sid, unsigned bg) {
    const int lane = threadIdx.x & 31, wid = threadIdx.x >> 5;
    const int buf = sid & 1;
    __syncthreads();
    double wd = warp_iscan_d(td, lane);
    if (lane == 31) sm->wd[wid] = wd;
    __syncthreads();
    if (wid == 0) {
        double vd = sm->wd[lane];
        double sd = warp_iscan_d(vd, lane);
        sm->wd[lane] = sd - vd;
        if (lane == 31) g_totd[buf][blockIdx.x] = sd;
    }
    grid_barrier(bg + (unsigned)sid + 1u);
    if (wid == 0) {
        double ad = 0.0;
#pragma unroll
        for (int j = lane; j < GRD; j += 32)
            if (j < (int)blockIdx.x) ad += g_totd[buf][j];
        ad = warp_sum_d(ad);
        if (lane == 0) sm->bd = ad;
    }
    __syncthreads();
    return sm->bd + sm->wd[wid] + (wd - td);
}

static __device__ void scan_fd(SMem* sm, float tf, double td, int sid,
                               unsigned bg, float& exf, double& exd) {
    const int lane = threadIdx.x & 31, wid = threadIdx.x >> 5;
    const int buf = sid & 1;
    __syncthreads();
    float wf = warp_iscan_f(tf, lane);
    double wd = warp_iscan_d(td, lane);
    if (lane == 31) { sm->wf[wid] = wf; sm->wd[wid] = wd; }
    __syncthreads();
    if (wid == 0) {
        float vf = sm->wf[lane];
        double vd = sm->wd[lane];
        float sf = warp_iscan_f(vf, lane);
        double sd = warp_iscan_d(vd, lane);
        sm->wf[lane] = sf - vf;
        sm->wd[lane] = sd - vd;
        if (lane == 31) { g_totf[buf][blockIdx.x] = sf; g_totd[buf][blockIdx.x] = sd; }
    }
    grid_barrier(bg + (unsigned)sid + 1u);
    if (wid == 0) {
        float af = 0.f; double ad = 0.0;
#pragma unroll
        for (int j = lane; j < GRD; j += 32)
            if (j < (int)blockIdx.x) { af += g_totf[buf][j]; ad += g_totd[buf][j]; }
        af = warp_sum_f(af); ad = warp_sum_d(ad);
        if (lane == 0) { sm->bf = af; sm->bd = ad; }
    }
    __syncthreads();
    exf = sm->bf + sm->wf[wid] + (wf - tf);
    exd = sm->bd + sm->wd[wid] + (wd - td);
}

static __device__ void scan_dd(SMem* sm, double ta, double tb, int sid,
                               unsigned bg, double& exa, double& exb) {
    const int lane = threadIdx.x & 31, wid = threadIdx.x >> 5;
    const int buf = sid & 1;
    __syncthreads();
    double wa = warp_iscan_d(ta, lane);
    double wb = warp_iscan_d(tb, lane);
    if (lane == 31) { sm->wd[wid] = wa; sm->wd2[wid] = wb; }
    __syncthreads();
    if (wid == 0) {
        double va = sm->wd[lane];
        double vb = sm->wd2[lane];
        double sa = warp_iscan_d(va, lane);
        double sb = warp_iscan_d(vb, lane);
        sm->wd[lane] = sa - va;
        sm->wd2[lane] = sb - vb;
        if (lane == 31) { g_totd[buf][blockIdx.x] = sa; g_totd2[buf][blockIdx.x] = sb; }
    }
    grid_barrier(bg + (unsigned)sid + 1u);
    if (wid == 0) {
        double aa = 0.0, ab = 0.0;
#pragma unroll
        for (int j = lane; j < GRD; j += 32)
            if (j < (int)blockIdx.x) { aa += g_totd[buf][j]; ab += g_totd2[buf][j]; }
        aa = warp_sum_d(aa); ab = warp_sum_d(ab);
        if (lane == 0) { sm->bd = aa; sm->bd2 = ab; }
    }
    __syncthreads();
    exa = sm->bd + sm->wd[wid] + (wa - ta);
    exb = sm->bd2 + sm->wd2[wid] + (wb - tb);
}

// f32-replicated field: psi = fl32(ku*z); 2-term Cody-Waite; fast cos.
static __device__ __forceinline__ float fval32(float kuf, float zf) {
    float psi = __fmul_rn(kuf, zf);
    float n = rintf(psi * 0.15915494309189535f);
    float r = fmaf(-n, 6.28125f, psi);
    r = fmaf(-n, 1.9353071795864769e-3f, r);
    return __cosf(r);
}

// fl32(ref + c) - ref modeled as ulp(ref)-grid rounding of c (all f32).
static __device__ __forceinline__ float qstepf(float c, float ref) {
    int e = (int)((__float_as_uint(fabsf(ref)) >> 23) & 0xffu);
    if (e < 24) return c;
    float u  = __uint_as_float((unsigned)(e - 23) << 23);   // 2^(e-150)
    float iu = __uint_as_float((unsigned)(277 - e) << 23);  // 2^(150-e)
    return u * rintf(c * iu);
}

__global__ void __launch_bounds__(TPB, 1) picard_all(
    const float* __restrict__ time, const float* __restrict__ r0v,
    const float* __restrict__ d0v, const float* __restrict__ gptr,
    const float* __restrict__ b0ptr, const float* __restrict__ kuptr,
    float* __restrict__ out, int N)
{
    __shared__ SMem sm;
    const int tid = threadIdx.x;
    if (tid == 0) sm.base = g_gen;
    __syncthreads();
    const unsigned bg = sm.base;

    // ---- scalars (f32-replicated initial momentum) ----
    const double dt = (double)(time[1] - time[0]);
    const double gamma = (double)gptr[0];
    const double B0 = (double)b0ptr[0];
    const float kuf = kuptr[0];
    float dxf = d0v[0], dyf = d0v[1], dzf = d0v[2];
    float gf = gptr[0];
    float dnf = sqrtf(dxf * dxf + dyf * dyf + dzf * dzf);
    float csf = 0.29979245f * sqrtf(gf * gf - 1.0f);
    const double px0 = (double)(csf * dxf / dnf);
    const double py0 = (double)(csf * dyf / dnf);
    const double pz0 = (double)(csf * dzf / dnf);
    const double x0 = (double)r0v[0], y0 = (double)r0v[1], z0 = (double)r0v[2];
    const double invg = 1.0 / gamma;
    const double Pmag = sqrt(px0 * px0 + pz0 * pz0);
    const double phi0 = atan2(px0, pz0);
    const float Kthf  = (float)(B0 * dt * invg);
    const float Kzf   = (float)(dt * invg * Pmag);
    const float phi0f = (float)phi0;
    const float f0f   = fval32(kuf, (float)z0);
    const double cy   = dt * py0 * invg;
    const float cyf   = (float)cy;
    const float y0f   = (float)y0;
    const float x0f   = (float)x0;
    const float scalef = (float)(Pmag / (0.29979245 * gamma));
    const float byc    = (float)(py0 / (0.29979245 * gamma));

    // secular-corrected ballistic init velocity:
    // vz(t) = (P/g) cos(phi0 + a(sin psi - sin psi0)); mean = (P/g) cos(b) J0(a)
    const double vz0d = pz0 * invg;
    const double ku_d = (double)kuf;
    const double a_amp = B0 * invg / (ku_d * vz0d);
    const double psi0 = ku_d * z0;
    const double bph = phi0 - a_amp * sin(psi0);
    const double j0a = 1.0 - 0.25 * a_amp * a_amp
                     + (a_amp * a_amp) * (a_amp * a_amp) / 64.0;
    const double vzmdt = Pmag * invg * cos(bph) * j0a * dt;

    const int base = ((int)blockIdx.x * TPB + tid) * EPT;
    const int blk0 = (int)blockIdx.x * TILE;

    float zf[EPT], fs[EPT], qs[EPT], cxs[EPT];
    int sid = 0;

    // ---- pre-final sweeps ----
#pragma unroll 1
    for (int sw = 0; sw < NPRE; ++sw) {
        float Tf = 0.f;
#pragma unroll
        for (int k = 0; k < EPT; ++k) {
            int i = base + k;
            if (sw == 0) zf[k] = (float)(z0 + vzmdt * (double)i);
            float f = (i < N) ? fval32(kuf, zf[k]) : 0.f;
            fs[k] = f; Tf += f;
        }
        float exf = scan_f(&sm, Tf, sid, bg); sid++;

        float Tq = 0.f; float run = exf;
#pragma unroll
        for (int k = 0; k < EPT; ++k) {
            int i = base + k;
            float f = fs[k];
            run += f;
            float th  = Kthf * (run - 0.5f * (f0f + f));
            float thm = fmaf(0.5f * Kthf, f, th);
            float u = phi0f + thm;
            float u2 = u * u;
            float cu = fmaf(u2, fmaf(u2, 1.f / 24.f, -0.5f), 1.f);
            float qf = (i < N) ? qstepf(Kzf * cu, zf[k]) : 0.f;
            fs[k] = qf;                       // reuse fs for q
            Tq += qf;                         // exact (grid multiples)
        }
        double exq = scan_d(&sm, (double)Tq, sid, bg); sid++;

        double basez = z0 + exq;
        float runq = 0.f;
#pragma unroll
        for (int k = 0; k < EPT; ++k) {
            zf[k] = (float)(basez + (double)runq);   // independent DADDs
            runq += fs[k];                           // exact f32 chain
        }
    }

    // ---- final sweep ----
    float Tf = 0.f;
#pragma unroll
    for (int k = 0; k < EPT; ++k) {
        int i = base + k;
        float f = (i < N) ? fval32(kuf, zf[k]) : 0.f;
        fs[k] = f; Tf += f;
    }
    float exf = scan_f(&sm, Tf, sid, bg); sid++;

    float Tq = 0.f, Tcx = 0.f; float run = exf;
#pragma unroll
    for (int k = 0; k < EPT; ++k) {
        int i = base + k;
        float f = fs[k];
        run += f;
        float th  = Kthf * (run - 0.5f * (f0f + f));
        float thm = fmaf(0.5f * Kthf, f, th);
        float u = phi0f + thm;
        float u2 = u * u;
        float cu = fmaf(u2, fmaf(u2, 1.f / 24.f, -0.5f), 1.f);
        float su = u * fmaf(u2, fmaf(u2, 1.f / 120.f, -1.f / 6.f), 1.f);
        float qf = (i < N) ? qstepf(Kzf * cu, zf[k]) : 0.f;
        float cx = (i < N) ? Kzf * su : 0.f;
        qs[k] = qf;   Tq += qf;
        cxs[k] = cx;  Tcx += cx;
        fs[k] = th;                            // keep node theta
    }
    float excx; double exq;
    scan_fd(&sm, Tcx, (double)Tq, sid, bg, excx, exq); sid++;

    float Tqx = 0.f, Tqy = 0.f;
    {
        double basez = z0 + exq;
        float runq = 0.f, runcx = excx;
#pragma unroll
        for (int k = 0; k < EPT; ++k) {
            int i = base + k;
            zf[k] = (float)(basez + (double)runq);
            runq += qs[k];
            float xpl = x0f + runcx;                 // plain x (binade ref)
            runcx += cxs[k];
            float qx = (i < N) ? qstepf(cxs[k], xpl) : 0.f;
            cxs[k] = qx;  Tqx += qx;
            float ypl = fmaf(cyf, (float)i, y0f);    // plain y (binade ref)
            float qy = (i < N) ? qstepf(cyf, ypl) : 0.f;
            qs[k] = qy;   Tqy += qy;
        }
    }
    double exqx, exqy;
    scan_dd(&sm, (double)Tqx, (double)Tqy, sid, bg, exqx, exqy); sid++;

    // ---- outputs (smem transpose, coalesced) ----
    const size_t Ns = (size_t)N;
    const int nrem = N - blk0;

    // x
    {
        double basex = x0 + exqx;
        float runqx = 0.f;
        __syncthreads();
#pragma unroll
        for (int k = 0; k < EPT; ++k) {
            sm.stage[tid * EPT + k] = (float)(basex + (double)runqx);
            runqx += cxs[k];
        }
        __syncthreads();
        for (int j = tid; j < TILE; j += TPB)
            if (j < nrem) out[blk0 + j] = sm.stage[j];
    }
    // y
    {
        double basey = y0 + exqy;
        float runqy = 0.f;
        __syncthreads();
#pragma unroll
        for (int k = 0; k < EPT; ++k) {
            sm.stage[tid * EPT + k] = (float)(basey + (double)runqy);
            runqy += qs[k];
        }
        __syncthreads();
        for (int j = tid; j < TILE; j += TPB)
            if (j < nrem) out[Ns + blk0 + j] = sm.stage[j];
    }
    // z
    {
        __syncthreads();
#pragma unroll
        for (int k = 0; k < EPT; ++k)
            sm.stage[tid * EPT + k] = zf[k];
        __syncthreads();
        for (int j = tid; j < TILE; j += TPB)
            if (j < nrem) out[2 * Ns + blk0 + j] = sm.stage[j];
    }
    // beta_x
    {
        __syncthreads();
#pragma unroll
        for (int k = 0; k < EPT; ++k) {
            float u = phi0f + fs[k];
            float u2 = u * u;
            float su = u * fmaf(u2, fmaf(u2, 1.f / 120.f, -1.f / 6.f), 1.f);
            sm.stage[tid * EPT + k] = scalef * su;
        }
        __syncthreads();
        for (int j = tid; j < TILE; j += TPB)
            if (j < nrem) out[3 * Ns + blk0 + j] = sm.stage[j];
    }
    // beta_y (constant)
    for (int j = tid; j < TILE; j += TPB)
        if (j < nrem) out[4 * Ns + blk0 + j] = byc;
    // beta_z
    {
        __syncthreads();
#pragma unroll
        for (int k = 0; k < EPT; ++k) {
            float u = phi0f + fs[k];
            float u2 = u * u;
            float cu = fmaf(u2, fmaf(u2, 1.f / 24.f, -0.5f), 1.f);
            sm.stage[tid * EPT + k] = scalef * cu;
        }
        __syncthreads();
        for (int j = tid; j < TILE; j += TPB)
            if (j < nrem) out[5 * Ns + blk0 + j] = sm.stage[j];
    }
}

// ---------------- serial fallback (N exceeds capacity) ---------------------
__global__ void __launch_bounds__(32, 1) track_seq_kernel(
    const float* __restrict__ time, const float* __restrict__ r0v,
    const float* __restrict__ d0v, const float* __restrict__ gptr,
    const float* __restrict__ b0ptr, const float* __restrict__ kuptr,
    float* __restrict__ out, int N)
{
    if (threadIdx.x != 0 || blockIdx.x != 0) return;
    const float C = 0.29979245f;
    const float dt = time[1] - time[0];
    const float dt2 = 0.5f * dt, h6 = dt * (1.0f / 6.0f);
    const float gamma = gptr[0], B0 = b0ptr[0], ku = kuptr[0];
    const float A = 1.0f / gamma;
    const float KdtA2 = ku * dt2 * A, KdtA = ku * dt * A;
    const float inv_cg = 1.0f / (C * gamma);
    float dx0 = d0v[0], dy0 = d0v[1], dz0 = d0v[2];
    float dn = sqrtf(dx0 * dx0 + dy0 * dy0 + dz0 * dz0);
    float pscale = C * sqrtf(gamma * gamma - 1.0f) / dn;
    float px = pscale * dx0, py = pscale * dy0, pz = pscale * dz0;
    float x = r0v[0], y = r0v[1], z = r0v[2];
    const float vy = py * A;
    float cps = cosf(ku * z), sps = sinf(ku * z);
    float Bc = B0 * cps, Bs = B0 * sps;
    const size_t Ns = (size_t)N;
    out[0] = x; out[Ns] = y; out[2 * Ns] = z;
    out[3 * Ns] = px * inv_cg; out[4 * Ns] = py * inv_cg; out[5 * Ns] = pz * inv_cg;
#pragma unroll 1
    for (int i = 1; i < N; ++i) {
        float vx1 = px * A, vz1 = pz * A;
        float apx1 = pz * Bc * A, apz1 = -px * Bc * A;
        float px2 = fmaf(apx1, dt2, px), pz2 = fmaf(apz1, dt2, pz);
        float d2 = KdtA2 * pz, q2 = d2 * d2;
        float sd2 = d2 * fmaf(-0.16666667f, q2, 1.0f), cd2 = fmaf(-0.5f, q2, 1.0f);
        float By2 = fmaf(Bc, cd2, -Bs * sd2);
        float vx2 = px2 * A, vz2 = pz2 * A;
        float apx2 = pz2 * By2 * A, apz2 = -px2 * By2 * A;
        float px3 = fmaf(apx2, dt2, px), pz3 = fmaf(apz2, dt2, pz);
        float d3 = KdtA2 * pz2, q3 = d3 * d3;
        float sd3 = d3 * fmaf(-0.16666667f, q3, 1.0f), cd3 = fmaf(-0.5f, q3, 1.0f);
        float By3 = fmaf(Bc, cd3, -Bs * sd3);
        float vx3 = px3 * A, vz3 = pz3 * A;
        float apx3 = pz3 * By3 * A, apz3 = -px3 * By3 * A;
        float px4 = fmaf(apx3, dt, px), pz4 = fmaf(apz3, dt, pz);
        float d4 = KdtA * pz3, q4 = d4 * d4;
        float sd4 = d4 * fmaf(-0.16666667f, q4, 1.0f), cd4 = fmaf(-0.5f, q4, 1.0f);
        float By4 = fmaf(Bc, cd4, -Bs * sd4);
        float vx4 = px4 * A, vz4 = pz4 * A;
        float apx4 = pz4 * By4 * A, apz4 = -px4 * By4 * A;
        float dxs = h6 * (vx1 + 2.0f * (vx2 + vx3) + vx4);
        float dzs = h6 * (vz1 + 2.0f * (vz2 + vz3) + vz4);
        px = px + h6 * (apx1 + 2.0f * (apx2 + apx3) + apx4);
        pz = pz + h6 * (apz1 + 2.0f * (apz2 + apz3) + apz4);
        x += dxs; y += dt * vy; z += dzs;
        float dp = ku * dzs, qp = dp * dp;
        float sdp = dp * fmaf(-0.16666667f, qp, 1.0f), cdp = fmaf(-0.5f, qp, 1.0f);
        float cn = fmaf(cps, cdp, -sps * sdp);
        float sn = fmaf(sps, cdp, cps * sdp);
        float nr = fmaf(cn, cn, sn * sn);
        float corr = fmaf(-0.5f, nr, 1.5f);
        cps = cn * corr; sps = sn * corr;
        Bc = B0 * cps; Bs = B0 * sps;
        out[i] = x; out[Ns + i] = y; out[2 * Ns + i] = z;
        out[3 * Ns + i] = px * inv_cg; out[4 * Ns + i] = py * inv_cg; out[5 * Ns + i] = pz * inv_cg;
    }
}

extern "C" void kernel_launch(void* const* d_in, const int* in_sizes, int n_in,
                              void* d_out, int out_size) {
    const float* time = (const float*)d_in[0];
    const float* r0   = (const float*)d_in[1];
    const float* d0   = (const float*)d_in[2];
    const float* gam  = (const float*)d_in[3];
    const float* B0   = (const float*)d_in[4];
    const float* ku   = (const float*)d_in[5];
    float* out = (float*)d_out;
    int N = in_sizes[0];

    if (N > CAP) {
        track_seq_kernel<<<1, 32>>>(time, r0, d0, gam, B0, ku, out, N);
        return;
    }
    picard_all<<<GRD, TPB>>>(time, r0, d0, gam, B0, ku, out, N);
}

// round 9
// speedup vs baseline: 1378.2633x; 1.9350x over previous
#include <cuda_runtime.h>
#include <cuda_bf16.h>

// Persistent single-launch parallel-in-time undulator tracker.
// FP64 minimized: scalar preamble (f64 transcendentals) computed ONCE per CTA
// and broadcast via smem; ladders use two-float (hi/lo) bases + exact-grid f32
// increments; f64 survives only in the cross-warp/grid scan network.

#define TPB 1024
#define GRD 148
#define EPT 7
#define TILE (TPB * EPT)          // 7168
#define CAP (TILE * GRD)          // 1,060,864
#define NPRE 2

__device__ volatile unsigned g_gen;   // monotonic across graph replays
__device__ unsigned g_cnt;
__device__ volatile float  g_totf[2][GRD];
__device__ volatile double g_totd[2][GRD];
__device__ volatile double g_totd2[2][GRD];

struct SCon {
    float kuf, Kthf, Kzf, phi0f, f0f, cyf, y0f, x0f, scalef, byc, vzmdtf;
    double z0, vzmdt, x0, y0;
};

struct SMem {
    SCon c;
    float  wf[32];
    double wd[32];
    double wd2[32];
    float  bf;
    double bd, bd2;
    unsigned base;
    float stage[TILE];            // 28 KB output transpose buffer
};

static __device__ __forceinline__ float warp_iscan_f(float v, int lane) {
#pragma unroll
    for (int d = 1; d < 32; d <<= 1) {
        float n = __shfl_up_sync(0xffffffffu, v, d);
        if (lane >= d) v += n;
    }
    return v;
}
static __device__ __forceinline__ double warp_iscan_d(double v, int lane) {
#pragma unroll
    for (int d = 1; d < 32; d <<= 1) {
        double n = __shfl_up_sync(0xffffffffu, v, d);
        if (lane >= d) v += n;
    }
    return v;
}
static __device__ __forceinline__ float warp_sum_f(float v) {
#pragma unroll
    for (int d = 16; d; d >>= 1) v += __shfl_down_sync(0xffffffffu, v, d);
    return v;
}
static __device__ __forceinline__ double warp_sum_d(double v) {
#pragma unroll
    for (int d = 16; d; d >>= 1) v += __shfl_down_sync(0xffffffffu, v, d);
    return v;
}

static __device__ __forceinline__ void grid_barrier(unsigned target) {
    __syncthreads();
    if (threadIdx.x == 0) {
        __threadfence();
        unsigned prev = atomicAdd(&g_cnt, 1u);
        if (prev == GRD - 1) {
            g_cnt = 0;
            __threadfence();
            g_gen = target;
        } else {
            while (g_gen != target) { }
            __threadfence();
        }
    }
    __syncthreads();
}

static __device__ float scan_f(SMem* sm, float tf, int sid, unsigned bg) {
    const int lane = threadIdx.x & 31, wid = threadIdx.x >> 5;
    const int buf = sid & 1;
    __syncthreads();
    float wf = warp_iscan_f(tf, lane);
    if (lane == 31) sm->wf[wid] = wf;
    __syncthreads();
    if (wid == 0) {
        float vf = sm->wf[lane];
        float sf = warp_iscan_f(vf, lane);
        sm->wf[lane] = sf - vf;
        if (lane == 31) g_totf[buf][blockIdx.x] = sf;
    }
    grid_barrier(bg + (unsigned)sid + 1u);
    if (wid == 0) {
        float af = 0.f;
#pragma unroll
        for (int j = lane; j < GRD; j += 32)
            if (j < (int)blockIdx.x) af += g_totf[buf][j];
        af = warp_sum_f(af);
        if (lane == 0) sm->bf = af;
    }
    __syncthreads();
    return sm->bf + sm->wf[wid] + (wf - tf);
}

static __device__ double scan_d(SMem* sm, double td, int sid, unsigned bg) {
    const int lane = threadIdx.x & 31, wid = threadIdx.x >> 5;
    const int buf = sid & 1;
    __syncthreads();
    double wd = warp_iscan_d(td, lane);
    if (lane == 31) sm->wd[wid] = wd;
    __syncthreads();
    if (wid == 0) {
        double vd = sm->wd[lane];
        double sd = warp_iscan_d(vd, lane);
        sm->wd[lane] = sd - vd;
        if (lane == 31) g_totd[buf][blockIdx.x] = sd;
    }
    grid_barrier(bg + (unsigned)sid + 1u);
    if (wid == 0) {
        double ad = 0.0;
#pragma unroll
        for (int j = lane; j < GRD; j += 32)
            if (j < (int)blockIdx.x) ad += g_totd[buf][j];
        ad = warp_sum_d(ad);
        if (lane == 0) sm->bd = ad;
    }
    __syncthreads();
    return sm->bd + sm->wd[wid] + (wd - td);
}

static __device__ void scan_fd(SMem* sm, float tf, double td, int sid,
                               unsigned bg, float& exf, double& exd) {
    const int lane = threadIdx.x & 31, wid = threadIdx.x >> 5;
    const int buf = sid & 1;
    __syncthreads();
    float wf = warp_iscan_f(tf, lane);
    double wd = warp_iscan_d(td, lane);
    if (lane == 31) { sm->wf[wid] = wf; sm->wd[wid] = wd; }
    __syncthreads();
    if (wid == 0) {
        float vf = sm->wf[lane];
        double vd = sm->wd[lane];
        float sf = warp_iscan_f(vf, lane);
        double sd = warp_iscan_d(vd, lane);
        sm->wf[lane] = sf - vf;
        sm->wd[lane] = sd - vd;
        if (lane == 31) { g_totf[buf][blockIdx.x] = sf; g_totd[buf][blockIdx.x] = sd; }
    }
    grid_barrier(bg + (unsigned)sid + 1u);
    if (wid == 0) {
        float af = 0.f; double ad = 0.0;
#pragma unroll
        for (int j = lane; j < GRD; j += 32)
            if (j < (int)blockIdx.x) { af += g_totf[buf][j]; ad += g_totd[buf][j]; }
        af = warp_sum_f(af); ad = warp_sum_d(ad);
        if (lane == 0) { sm->bf = af; sm->bd = ad; }
    }
    __syncthreads();
    exf = sm->bf + sm->wf[wid] + (wf - tf);
    exd = sm->bd + sm->wd[wid] + (wd - td);
}

static __device__ void scan_dd(SMem* sm, double ta, double tb, int sid,
                               unsigned bg, double& exa, double& exb) {
    const int lane = threadIdx.x & 31, wid = threadIdx.x >> 5;
    const int buf = sid & 1;
    __syncthreads();
    double wa = warp_iscan_d(ta, lane);
    double wb = warp_iscan_d(tb, lane);
    if (lane == 31) { sm->wd[wid] = wa; sm->wd2[wid] = wb; }
    __syncthreads();
    if (wid == 0) {
        double va = sm->wd[lane];
        double vb = sm->wd2[lane];
        double sa = warp_iscan_d(va, lane);
        double sb = warp_iscan_d(vb, lane);
        sm->wd[lane] = sa - va;
        sm->wd2[lane] = sb - vb;
        if (lane == 31) { g_totd[buf][blockIdx.x] = sa; g_totd2[buf][blockIdx.x] = sb; }
    }
    grid_barrier(bg + (unsigned)sid + 1u);
    if (wid == 0) {
        double aa = 0.0, ab = 0.0;
#pragma unroll
        for (int j = lane; j < GRD; j += 32)
            if (j < (int)blockIdx.x) { aa += g_totd[buf][j]; ab += g_totd2[buf][j]; }
        aa = warp_sum_d(aa); ab = warp_sum_d(ab);
        if (lane == 0) { sm->bd = aa; sm->bd2 = ab; }
    }
    __syncthreads();
    exa = sm->bd + sm->wd[wid] + (wa - ta);
    exb = sm->bd2 + sm->wd2[wid] + (wb - tb);
}

// f32-replicated field: psi = fl32(ku*z); 2-term Cody-Waite; fast cos.
static __device__ __forceinline__ float fval32(float kuf, float zf) {
    float psi = __fmul_rn(kuf, zf);
    float n = rintf(psi * 0.15915494309189535f);
    float r = fmaf(-n, 6.28125f, psi);
    r = fmaf(-n, 1.9353071795864769e-3f, r);
    return __cosf(r);
}

// fl32(ref + c) - ref modeled as ulp(ref)-grid rounding of c (all f32).
static __device__ __forceinline__ float qstepf(float c, float ref) {
    int e = (int)((__float_as_uint(fabsf(ref)) >> 23) & 0xffu);
    if (e < 24) return c;
    float u  = __uint_as_float((unsigned)(e - 23) << 23);   // 2^(e-150)
    float iu = __uint_as_float((unsigned)(277 - e) << 23);  // 2^(150-e)
    return u * rintf(c * iu);
}

__global__ void __launch_bounds__(TPB, 1) picard_all(
    const float* __restrict__ time, const float* __restrict__ r0v,
    const float* __restrict__ d0v, const float* __restrict__ gptr,
    const float* __restrict__ b0ptr, const float* __restrict__ kuptr,
    float* __restrict__ out, int N)
{
    __shared__ SMem sm;
    const int tid = threadIdx.x;

    // ---- preamble: ONCE per CTA (f64 transcendentals are SM-throughput poison)
    if (tid == 0) {
        sm.base = g_gen;
        const double dt = (double)(time[1] - time[0]);
        const double gamma = (double)gptr[0];
        const double B0 = (double)b0ptr[0];
        const float kuf = kuptr[0];
        float dxf = d0v[0], dyf = d0v[1], dzf = d0v[2];
        float gf = gptr[0];
        float dnf = sqrtf(dxf * dxf + dyf * dyf + dzf * dzf);
        float csf = 0.29979245f * sqrtf(gf * gf - 1.0f);
        const double px0 = (double)(csf * dxf / dnf);
        const double py0 = (double)(csf * dyf / dnf);
        const double pz0 = (double)(csf * dzf / dnf);
        const double x0 = (double)r0v[0], y0 = (double)r0v[1], z0 = (double)r0v[2];
        const double invg = 1.0 / gamma;
        const double Pmag = sqrt(px0 * px0 + pz0 * pz0);
        const double phi0 = atan2(px0, pz0);
        const double cy = dt * py0 * invg;
        // secular-corrected ballistic mean velocity
        const double vz0d = pz0 * invg;
        const double ku_d = (double)kuf;
        const double a_amp = B0 * invg / (ku_d * vz0d);
        const double psi0 = ku_d * z0;
        const double bph = phi0 - a_amp * sin(psi0);
        const double a2 = a_amp * a_amp;
        const double j0a = 1.0 - 0.25 * a2 + a2 * a2 / 64.0;
        const double vzmdt = Pmag * invg * cos(bph) * j0a * dt;

        sm.c.kuf = kuf;
        sm.c.Kthf = (float)(B0 * dt * invg);
        sm.c.Kzf  = (float)(dt * invg * Pmag);
        sm.c.phi0f = (float)phi0;
        sm.c.f0f = fval32(kuf, (float)z0);
        sm.c.cyf = (float)cy;
        sm.c.y0f = (float)y0;
        sm.c.x0f = (float)x0;
        sm.c.scalef = (float)(Pmag / (0.29979245 * gamma));
        sm.c.byc    = (float)(py0 / (0.29979245 * gamma));
        sm.c.vzmdtf = (float)vzmdt;
        sm.c.z0 = z0; sm.c.vzmdt = vzmdt; sm.c.x0 = x0; sm.c.y0 = y0;
    }
    __syncthreads();

    const unsigned bg = sm.base;
    const float kuf = sm.c.kuf, Kthf = sm.c.Kthf, Kzf = sm.c.Kzf;
    const float phi0f = sm.c.phi0f, f0f = sm.c.f0f, cyf = sm.c.cyf;
    const float y0f = sm.c.y0f, x0f = sm.c.x0f;
    const float scalef = sm.c.scalef, byc = sm.c.byc, vzmdtf = sm.c.vzmdtf;
    const double z0 = sm.c.z0;

    const int base = ((int)blockIdx.x * TPB + tid) * EPT;
    const int blk0 = (int)blockIdx.x * TILE;

    float zf[EPT], fs[EPT], qs[EPT], cxs[EPT];
    int sid = 0;

    // ballistic init base (2 f64 ops per thread, then pure f32)
    {
        double zb = z0 + sm.c.vzmdt * (double)base;
        float zbhi = (float)zb;
        float zblo = (float)(zb - (double)zbhi);
#pragma unroll
        for (int k = 0; k < EPT; ++k)
            zf[k] = zbhi + (zblo + (float)k * vzmdtf);
    }

    // ---- pre-final sweeps ----
#pragma unroll 1
    for (int sw = 0; sw < NPRE; ++sw) {
        float Tf = 0.f;
#pragma unroll
        for (int k = 0; k < EPT; ++k) {
            int i = base + k;
            float f = (i < N) ? fval32(kuf, zf[k]) : 0.f;
            fs[k] = f; Tf += f;
        }
        float exf = scan_f(&sm, Tf, sid, bg); sid++;

        float Tq = 0.f; float run = exf;
#pragma unroll
        for (int k = 0; k < EPT; ++k) {
            int i = base + k;
            float f = fs[k];
            run += f;
            float th  = Kthf * (run - 0.5f * (f0f + f));
            float thm = fmaf(0.5f * Kthf, f, th);
            float u = phi0f + thm;
            float u2 = u * u;
            float cu = fmaf(u2, fmaf(u2, 1.f / 24.f, -0.5f), 1.f);
            float qf = (i < N) ? qstepf(Kzf * cu, zf[k]) : 0.f;
            fs[k] = qf;                       // reuse fs for q
            Tq += qf;                         // exact (grid multiples)
        }
        double exq = scan_d(&sm, (double)Tq, sid, bg); sid++;

        // two-float base: 2 f64 ops per thread per sweep
        double basez = z0 + exq;
        float bzhi = (float)basez;
        float bzlo = (float)(basez - (double)bzhi);
        float runq = 0.f;
#pragma unroll
        for (int k = 0; k < EPT; ++k) {
            zf[k] = bzhi + (bzlo + runq);
            runq += fs[k];                    // exact f32 chain
        }
    }

    // ---- final sweep ----
    float Tf = 0.f;
#pragma unroll
    for (int k = 0; k < EPT; ++k) {
        int i = base + k;
        float f = (i < N) ? fval32(kuf, zf[k]) : 0.f;
        fs[k] = f; Tf += f;
    }
    float exf = scan_f(&sm, Tf, sid, bg); sid++;

    float Tq = 0.f, Tcx = 0.f; float run = exf;
#pragma unroll
    for (int k = 0; k < EPT; ++k) {
        int i = base + k;
        float f = fs[k];
        run += f;
        float th  = Kthf * (run - 0.5f * (f0f + f));
        float thm = fmaf(0.5f * Kthf, f, th);
        float u = phi0f + thm;
        float u2 = u * u;
        float cu = fmaf(u2, fmaf(u2, 1.f / 24.f, -0.5f), 1.f);
        float su = u * fmaf(u2, fmaf(u2, 1.f / 120.f, -1.f / 6.f), 1.f);
        float qf = (i < N) ? qstepf(Kzf * cu, zf[k]) : 0.f;
        float cx = (i < N) ? Kzf * su : 0.f;
        qs[k] = qf;   Tq += qf;
        cxs[k] = cx;  Tcx += cx;
        fs[k] = th;                            // keep node theta
    }
    float excx; double exq;
    scan_fd(&sm, Tcx, (double)Tq, sid, bg, excx, exq); sid++;

    float Tqx = 0.f, Tqy = 0.f;
    {
        double basez = z0 + exq;
        float bzhi = (float)basez;
        float bzlo = (float)(basez - (double)bzhi);
        float runq = 0.f, runcx = excx;
#pragma unroll
        for (int k = 0; k < EPT; ++k) {
            int i = base + k;
            zf[k] = bzhi + (bzlo + runq);
            runq += qs[k];
            float xpl = x0f + runcx;                 // plain x (binade ref)
            runcx += cxs[k];
            float qx = (i < N) ? qstepf(cxs[k], xpl) : 0.f;
            cxs[k] = qx;  Tqx += qx;
            float ypl = fmaf(cyf, (float)i, y0f);    // plain y (binade ref)
            float qy = (i < N) ? qstepf(cyf, ypl) : 0.f;
            qs[k] = qy;   Tqy += qy;
        }
    }
    double exqx, exqy;
    scan_dd(&sm, (double)Tqx, (double)Tqy, sid, bg, exqx, exqy); sid++;

    // ---- outputs (smem transpose, coalesced) ----
    const size_t Ns = (size_t)N;
    const int nrem = N - blk0;

    // x
    {
        double basex = sm.c.x0 + exqx;
        float bxhi = (float)basex;
        float bxlo = (float)(basex - (double)bxhi);
        float runqx = 0.f;
        __syncthreads();
#pragma unroll
        for (int k = 0; k < EPT; ++k) {
            sm.stage[tid * EPT + k] = bxhi + (bxlo + runqx);
            runqx += cxs[k];
        }
        __syncthreads();
        for (int j = tid; j < TILE; j += TPB)
            if (j < nrem) out[blk0 + j] = sm.stage[j];
    }
    // y
    {
        double basey = sm.c.y0 + exqy;
        float byhi = (float)basey;
        float bylo = (float)(basey - (double)byhi);
        float runqy = 0.f;
        __syncthreads();
#pragma unroll
        for (int k = 0; k < EPT; ++k) {
            sm.stage[tid * EPT + k] = byhi + (bylo + runqy);
            runqy += qs[k];
        }
        __syncthreads();
        for (int j = tid; j < TILE; j += TPB)
            if (j < nrem) out[Ns + blk0 + j] = sm.stage[j];
    }
    // z
    {
        __syncthreads();
#pragma unroll
        for (int k = 0; k < EPT; ++k)
            sm.stage[tid * EPT + k] = zf[k];
        __syncthreads();
        for (int j = tid; j < TILE; j += TPB)
            if (j < nrem) out[2 * Ns + blk0 + j] = sm.stage[j];
    }
    // beta_x
    {
        __syncthreads();
#pragma unroll
        for (int k = 0; k < EPT; ++k) {
            float u = phi0f + fs[k];
            float u2 = u * u;
            float su = u * fmaf(u2, fmaf(u2, 1.f / 120.f, -1.f / 6.f), 1.f);
            sm.stage[tid * EPT + k] = scalef * su;
        }
        __syncthreads();
        for (int j = tid; j < TILE; j += TPB)
            if (j < nrem) out[3 * Ns + blk0 + j] = sm.stage[j];
    }
    // beta_y (constant)
    for (int j = tid; j < TILE; j += TPB)
        if (j < nrem) out[4 * Ns + blk0 + j] = byc;
    // beta_z
    {
        __syncthreads();
#pragma unroll
        for (int k = 0; k < EPT; ++k) {
            float u = phi0f + fs[k];
            float u2 = u * u;
            float cu = fmaf(u2, fmaf(u2, 1.f / 24.f, -0.5f), 1.f);
            sm.stage[tid * EPT + k] = scalef * cu;
        }
        __syncthreads();
        for (int j = tid; j < TILE; j += TPB)
            if (j < nrem) out[5 * Ns + blk0 + j] = sm.stage[j];
    }
}

// ---------------- serial fallback (N exceeds capacity) ---------------------
__global__ void __launch_bounds__(32, 1) track_seq_kernel(
    const float* __restrict__ time, const float* __restrict__ r0v,
    const float* __restrict__ d0v, const float* __restrict__ gptr,
    const float* __restrict__ b0ptr, const float* __restrict__ kuptr,
    float* __restrict__ out, int N)
{
    if (threadIdx.x != 0 || blockIdx.x != 0) return;
    const float C = 0.29979245f;
    const float dt = time[1] - time[0];
    const float dt2 = 0.5f * dt, h6 = dt * (1.0f / 6.0f);
    const float gamma = gptr[0], B0 = b0ptr[0], ku = kuptr[0];
    const float A = 1.0f / gamma;
    const float KdtA2 = ku * dt2 * A, KdtA = ku * dt * A;
    const float inv_cg = 1.0f / (C * gamma);
    float dx0 = d0v[0], dy0 = d0v[1], dz0 = d0v[2];
    float dn = sqrtf(dx0 * dx0 + dy0 * dy0 + dz0 * dz0);
    float pscale = C * sqrtf(gamma * gamma - 1.0f) / dn;
    float px = pscale * dx0, py = pscale * dy0, pz = pscale * dz0;
    float x = r0v[0], y = r0v[1], z = r0v[2];
    const float vy = py * A;
    float cps = cosf(ku * z), sps = sinf(ku * z);
    float Bc = B0 * cps, Bs = B0 * sps;
    const size_t Ns = (size_t)N;
    out[0] = x; out[Ns] = y; out[2 * Ns] = z;
    out[3 * Ns] = px * inv_cg; out[4 * Ns] = py * inv_cg; out[5 * Ns] = pz * inv_cg;
#pragma unroll 1
    for (int i = 1; i < N; ++i) {
        float vx1 = px * A, vz1 = pz * A;
        float apx1 = pz * Bc * A, apz1 = -px * Bc * A;
        float px2 = fmaf(apx1, dt2, px), pz2 = fmaf(apz1, dt2, pz);
        float d2 = KdtA2 * pz, q2 = d2 * d2;
        float sd2 = d2 * fmaf(-0.16666667f, q2, 1.0f), cd2 = fmaf(-0.5f, q2, 1.0f);
        float By2 = fmaf(Bc, cd2, -Bs * sd2);
        float vx2 = px2 * A, vz2 = pz2 * A;
        float apx2 = pz2 * By2 * A, apz2 = -px2 * By2 * A;
        float px3 = fmaf(apx2, dt2, px), pz3 = fmaf(apz2, dt2, pz);
        float d3 = KdtA2 * pz2, q3 = d3 * d3;
        float sd3 = d3 * fmaf(-0.16666667f, q3, 1.0f), cd3 = fmaf(-0.5f, q3, 1.0f);
        float By3 = fmaf(Bc, cd3, -Bs * sd3);
        float vx3 = px3 * A, vz3 = pz3 * A;
        float apx3 = pz3 * By3 * A, apz3 = -px3 * By3 * A;
        float px4 = fmaf(apx3, dt, px), pz4 = fmaf(apz3, dt, pz);
        float d4 = KdtA * pz3, q4 = d4 * d4;
        float sd4 = d4 * fmaf(-0.16666667f, q4, 1.0f), cd4 = fmaf(-0.5f, q4, 1.0f);
        float By4 = fmaf(Bc, cd4, -Bs * sd4);
        float vx4 = px4 * A, vz4 = pz4 * A;
        float apx4 = pz4 * By4 * A, apz4 = -px4 * By4 * A;
        float dxs = h6 * (vx1 + 2.0f * (vx2 + vx3) + vx4);
        float dzs = h6 * (vz1 + 2.0f * (vz2 + vz3) + vz4);
        px = px + h6 * (apx1 + 2.0f * (apx2 + apx3) + apx4);
        pz = pz + h6 * (apz1 + 2.0f * (apz2 + apz3) + apz4);
        x += dxs; y += dt * vy; z += dzs;
        float dp = ku * dzs, qp = dp * dp;
        float sdp = dp * fmaf(-0.16666667f, qp, 1.0f), cdp = fmaf(-0.5f, qp, 1.0f);
        float cn = fmaf(cps, cdp, -sps * sdp);
        float sn = fmaf(sps, cdp, cps * sdp);
        float nr = fmaf(cn, cn, sn * sn);
        float corr = fmaf(-0.5f, nr, 1.5f);
        cps = cn * corr; sps = sn * corr;
        Bc = B0 * cps; Bs = B0 * sps;
        out[i] = x; out[Ns + i] = y; out[2 * Ns + i] = z;
        out[3 * Ns + i] = px * inv_cg; out[4 * Ns + i] = py * inv_cg; out[5 * Ns + i] = pz * inv_cg;
    }
}

extern "C" void kernel_launch(void* const* d_in, const int* in_sizes, int n_in,
                              void* d_out, int out_size) {
    const float* time = (const float*)d_in[0];
    const float* r0   = (const float*)d_in[1];
    const float* d0   = (const float*)d_in[2];
    const float* gam  = (const float*)d_in[3];
    const float* B0   = (const float*)d_in[4];
    const float* ku   = (const float*)d_in[5];
    float* out = (float*)d_out;
    int N = in_sizes[0];

    if (N > CAP) {
        track_seq_kernel<<<1, 32>>>(time, r0, d0, gam, B0, ku, out, N);
        return;
    }
    picard_all<<<GRD, TPB>>>(time, r0, d0, gam, B0, ku, out, N);
}

// round 12
// speedup vs baseline: 2078.9897x; 1.5084x over previous
#include <cuda_runtime.h>
#include <cuda_bf16.h>

// Persistent single-launch parallel-in-time undulator tracker.
// Init Picard iterate is ANALYTIC (secular ballistic path => closed-form
// theta), so only its q-ladder needs a scan. Final sweep replicates the
// reference's f32 quantized accumulation. 4 grid barriers total.
// R11 fix: 16B-align the smem staging buffer (float4 LDS.128 trapped at +8).

#define TPB 1024
#define GRD 148
#define EPT 7
#define TILE (TPB * EPT)          // 7168
#define CAP (TILE * GRD)          // 1,060,864

__device__ volatile unsigned g_gen;   // monotonic across graph replays
__device__ unsigned g_cnt;
__device__ volatile float  g_totf[2][GRD];
__device__ volatile float  g_totf2[2][GRD];
__device__ volatile double g_totd[2][GRD];

struct SCon {
    float kuf, Kthf, Kzf, phi0f, f0f, cyf, y0f, x0f, scalef, byc, vzmdtf;
    float aampf, spsi0f;
    double z0, vzmdt, x0, y0;
};

struct SMem {
    __align__(16) float stage[2][TILE];   // 56 KB output transpose buffers
    SCon c;
    float  wf[32], wf2[32];
    double wd[32];
    float  bf, bf2;
    double bd;
    unsigned base;
};

static __device__ __forceinline__ float warp_iscan_f(float v, int lane) {
#pragma unroll
    for (int d = 1; d < 32; d <<= 1) {
        float n = __shfl_up_sync(0xffffffffu, v, d);
        if (lane >= d) v += n;
    }
    return v;
}
static __device__ __forceinline__ double warp_iscan_d(double v, int lane) {
#pragma unroll
    for (int d = 1; d < 32; d <<= 1) {
        double n = __shfl_up_sync(0xffffffffu, v, d);
        if (lane >= d) v += n;
    }
    return v;
}
static __device__ __forceinline__ float warp_sum_f(float v) {
#pragma unroll
    for (int d = 16; d; d >>= 1) v += __shfl_down_sync(0xffffffffu, v, d);
    return v;
}
static __device__ __forceinline__ double warp_sum_d(double v) {
#pragma unroll
    for (int d = 16; d; d >>= 1) v += __shfl_down_sync(0xffffffffu, v, d);
    return v;
}

static __device__ __forceinline__ void grid_barrier(unsigned target) {
    __syncthreads();
    if (threadIdx.x == 0) {
        __threadfence();
        unsigned prev = atomicAdd(&g_cnt, 1u);
        if (prev == GRD - 1) {
            g_cnt = 0;
            __threadfence();
            g_gen = target;
        } else {
            while (g_gen != target) { }
            __threadfence();
        }
    }
    __syncthreads();
}

static __device__ float scan_f(SMem* sm, float tf, int sid, unsigned bg) {
    const int lane = threadIdx.x & 31, wid = threadIdx.x >> 5;
    const int buf = sid & 1;
    __syncthreads();
    float wf = warp_iscan_f(tf, lane);
    if (lane == 31) sm->wf[wid] = wf;
    __syncthreads();
    if (wid == 0) {
        float vf = sm->wf[lane];
        float sf = warp_iscan_f(vf, lane);
        sm->wf[lane] = sf - vf;
        if (lane == 31) g_totf[buf][blockIdx.x] = sf;
    }
    grid_barrier(bg + (unsigned)sid + 1u);
    if (wid == 0) {
        float af = 0.f;
#pragma unroll
        for (int j = lane; j < GRD; j += 32)
            if (j < (int)blockIdx.x) af += g_totf[buf][j];
        af = warp_sum_f(af);
        if (lane == 0) sm->bf = af;
    }
    __syncthreads();
    return sm->bf + sm->wf[wid] + (wf - tf);
}

static __device__ double scan_d(SMem* sm, double td, int sid, unsigned bg) {
    const int lane = threadIdx.x & 31, wid = threadIdx.x >> 5;
    const int buf = sid & 1;
    __syncthreads();
    double wd = warp_iscan_d(td, lane);
    if (lane == 31) sm->wd[wid] = wd;
    __syncthreads();
    if (wid == 0) {
        double vd = sm->wd[lane];
        double sd = warp_iscan_d(vd, lane);
        sm->wd[lane] = sd - vd;
        if (lane == 31) g_totd[buf][blockIdx.x] = sd;
    }
    grid_barrier(bg + (unsigned)sid + 1u);
    if (wid == 0) {
        double ad = 0.0;
#pragma unroll
        for (int j = lane; j < GRD; j += 32)
            if (j < (int)blockIdx.x) ad += g_totd[buf][j];
        ad = warp_sum_d(ad);
        if (lane == 0) sm->bd = ad;
    }
    __syncthreads();
    return sm->bd + sm->wd[wid] + (wd - td);
}

static __device__ void scan_fd(SMem* sm, float tf, double td, int sid,
                               unsigned bg, float& exf, double& exd) {
    const int lane = threadIdx.x & 31, wid = threadIdx.x >> 5;
    const int buf = sid & 1;
    __syncthreads();
    float wf = warp_iscan_f(tf, lane);
    double wd = warp_iscan_d(td, lane);
    if (lane == 31) { sm->wf[wid] = wf; sm->wd[wid] = wd; }
    __syncthreads();
    if (wid == 0) {
        float vf = sm->wf[lane];
        double vd = sm->wd[lane];
        float sf = warp_iscan_f(vf, lane);
        double sd = warp_iscan_d(vd, lane);
        sm->wf[lane] = sf - vf;
        sm->wd[lane] = sd - vd;
        if (lane == 31) { g_totf[buf][blockIdx.x] = sf; g_totd[buf][blockIdx.x] = sd; }
    }
    grid_barrier(bg + (unsigned)sid + 1u);
    if (wid == 0) {
        float af = 0.f; double ad = 0.0;
#pragma unroll
        for (int j = lane; j < GRD; j += 32)
            if (j < (int)blockIdx.x) { af += g_totf[buf][j]; ad += g_totd[buf][j]; }
        af = warp_sum_f(af); ad = warp_sum_d(ad);
        if (lane == 0) { sm->bf = af; sm->bd = ad; }
    }
    __syncthreads();
    exf = sm->bf + sm->wf[wid] + (wf - tf);
    exd = sm->bd + sm->wd[wid] + (wd - td);
}

static __device__ void scan_ff(SMem* sm, float ta, float tb, int sid,
                               unsigned bg, float& exa, float& exb) {
    const int lane = threadIdx.x & 31, wid = threadIdx.x >> 5;
    const int buf = sid & 1;
    __syncthreads();
    float wa = warp_iscan_f(ta, lane);
    float wb = warp_iscan_f(tb, lane);
    if (lane == 31) { sm->wf[wid] = wa; sm->wf2[wid] = wb; }
    __syncthreads();
    if (wid == 0) {
        float va = sm->wf[lane];
        float vb = sm->wf2[lane];
        float sa = warp_iscan_f(va, lane);
        float sb = warp_iscan_f(vb, lane);
        sm->wf[lane] = sa - va;
        sm->wf2[lane] = sb - vb;
        if (lane == 31) { g_totf[buf][blockIdx.x] = sa; g_totf2[buf][blockIdx.x] = sb; }
    }
    grid_barrier(bg + (unsigned)sid + 1u);
    if (wid == 0) {
        float aa = 0.f, ab = 0.f;
#pragma unroll
        for (int j = lane; j < GRD; j += 32)
            if (j < (int)blockIdx.x) { aa += g_totf[buf][j]; ab += g_totf2[buf][j]; }
        aa = warp_sum_f(aa); ab = warp_sum_f(ab);
        if (lane == 0) { sm->bf = aa; sm->bf2 = ab; }
    }
    __syncthreads();
    exa = sm->bf + sm->wf[wid] + (wa - ta);
    exb = sm->bf2 + sm->wf2[wid] + (wb - tb);
}

// f32-replicated field: psi = fl32(ku*z); 2-term Cody-Waite; fast cos.
static __device__ __forceinline__ float fval32(float kuf, float zf) {
    float psi = __fmul_rn(kuf, zf);
    float n = rintf(psi * 0.15915494309189535f);
    float r = fmaf(-n, 6.28125f, psi);
    r = fmaf(-n, 1.9353071795864769e-3f, r);
    return __cosf(r);
}
// sin(ku*z) for the analytic init (accuracy, not replication).
static __device__ __forceinline__ float sval32(float kuf, float zf) {
    float psi = __fmul_rn(kuf, zf);
    float n = rintf(psi * 0.15915494309189535f);
    float r = fmaf(-n, 6.28125f, psi);
    r = fmaf(-n, 1.9353071795864769e-3f, r);
    return __sinf(r);
}

// fl32(ref + c) - ref modeled as ulp(ref)-grid rounding of c (all f32).
static __device__ __forceinline__ float qstepf(float c, float ref) {
    int e = (int)((__float_as_uint(fabsf(ref)) >> 23) & 0xffu);
    if (e < 24) return c;
    float u  = __uint_as_float((unsigned)(e - 23) << 23);   // 2^(e-150)
    float iu = __uint_as_float((unsigned)(277 - e) << 23);  // 2^(150-e)
    return u * rintf(c * iu);
}

__global__ void __launch_bounds__(TPB, 1) picard_all(
    const float* __restrict__ time, const float* __restrict__ r0v,
    const float* __restrict__ d0v, const float* __restrict__ gptr,
    const float* __restrict__ b0ptr, const float* __restrict__ kuptr,
    float* __restrict__ out, int N)
{
    __shared__ SMem sm;
    const int tid = threadIdx.x;

    // ---- preamble: once per CTA (f64 transcendentals) ----
    if (tid == 0) {
        sm.base = g_gen;
        const double dt = (double)(time[1] - time[0]);
        const double gamma = (double)gptr[0];
        const double B0 = (double)b0ptr[0];
        const float kuf = kuptr[0];
        float dxf = d0v[0], dyf = d0v[1], dzf = d0v[2];
        float gf = gptr[0];
        float dnf = sqrtf(dxf * dxf + dyf * dyf + dzf * dzf);
        float csf = 0.29979245f * sqrtf(gf * gf - 1.0f);
        const double px0 = (double)(csf * dxf / dnf);
        const double py0 = (double)(csf * dyf / dnf);
        const double pz0 = (double)(csf * dzf / dnf);
        const double x0 = (double)r0v[0], y0 = (double)r0v[1], z0 = (double)r0v[2];
        const double invg = 1.0 / gamma;
        const double Pmag = sqrt(px0 * px0 + pz0 * pz0);
        const double phi0 = atan2(px0, pz0);
        const double cy = dt * py0 * invg;
        const double ku_d = (double)kuf;
        const double psi0 = ku_d * z0;
        // secular-corrected ballistic mean velocity
        const double vz0d = pz0 * invg;
        const double a0 = B0 * invg / (ku_d * vz0d);
        const double bph = phi0 - a0 * sin(psi0);
        const double a2 = a0 * a0;
        const double j0a = 1.0 - 0.25 * a2 + a2 * a2 / 64.0;
        const double vzm = Pmag * invg * cos(bph) * j0a;
        const double vzmdt = vzm * dt;
        const double aamp = B0 * invg / (ku_d * vzm);   // analytic theta amplitude

        sm.c.kuf = kuf;
        sm.c.Kthf = (float)(B0 * dt * invg);
        sm.c.Kzf  = (float)(dt * invg * Pmag);
        sm.c.phi0f = (float)phi0;
        sm.c.f0f = fval32(kuf, (float)z0);
        sm.c.cyf = (float)cy;
        sm.c.y0f = (float)y0;
        sm.c.x0f = (float)x0;
        sm.c.scalef = (float)(Pmag / (0.29979245 * gamma));
        sm.c.byc    = (float)(py0 / (0.29979245 * gamma));
        sm.c.vzmdtf = (float)vzmdt;
        sm.c.aampf  = (float)aamp;
        sm.c.spsi0f = (float)sin(psi0);
        sm.c.z0 = z0; sm.c.vzmdt = vzmdt; sm.c.x0 = x0; sm.c.y0 = y0;
    }
    __syncthreads();

    const unsigned bg = sm.base;
    const float kuf = sm.c.kuf, Kthf = sm.c.Kthf, Kzf = sm.c.Kzf;
    const float phi0f = sm.c.phi0f, f0f = sm.c.f0f, cyf = sm.c.cyf;
    const float y0f = sm.c.y0f, x0f = sm.c.x0f;
    const float scalef = sm.c.scalef, byc = sm.c.byc, vzmdtf = sm.c.vzmdtf;
    const float aampf = sm.c.aampf, spsi0f = sm.c.spsi0f;
    const double z0 = sm.c.z0;

    const int base = ((int)blockIdx.x * TPB + tid) * EPT;
    const int blk0 = (int)blockIdx.x * TILE;

    float zf[EPT], fs[EPT], qs[EPT], cxs[EPT];
    int sid = 0;

    // ---- init: analytic Picard-1 (no f-scan; 1 q-scan) ----
    {
        double zb = z0 + sm.c.vzmdt * (double)base;
        float zbhi = (float)zb;
        float zblo = (float)(zb - (double)zbhi);
        float Tq = 0.f;
#pragma unroll
        for (int k = 0; k < EPT; ++k) {
            int i = base + k;
            float zball = zbhi + (zblo + (float)k * vzmdtf);
            float zmid  = zbhi + (zblo + ((float)k + 0.5f) * vzmdtf);
            float th = aampf * (sval32(kuf, zmid) - spsi0f);
            float u = phi0f + th;
            float u2 = u * u;
            float cu = fmaf(u2, fmaf(u2, 1.f / 24.f, -0.5f), 1.f);
            float qf = (i < N) ? qstepf(Kzf * cu, zball) : 0.f;
            qs[k] = qf;
            Tq += qf;                          // exact (grid multiples)
        }
        double exq = scan_d(&sm, (double)Tq, sid, bg); sid++;

        double basez = z0 + exq;
        float bzhi = (float)basez;
        float bzlo = (float)(basez - (double)bzhi);
        float runq = 0.f;
#pragma unroll
        for (int k = 0; k < EPT; ++k) {
            zf[k] = bzhi + (bzlo + runq);
            runq += qs[k];                     // exact f32 chain
        }
    }

    // ---- final sweep ----
    float Tf = 0.f;
#pragma unroll
    for (int k = 0; k < EPT; ++k) {
        int i = base + k;
        float f = (i < N) ? fval32(kuf, zf[k]) : 0.f;
        fs[k] = f; Tf += f;
    }
    float exf = scan_f(&sm, Tf, sid, bg); sid++;

    float Tq = 0.f, Tcx = 0.f; float run = exf;
#pragma unroll
    for (int k = 0; k < EPT; ++k) {
        int i = base + k;
        float f = fs[k];
        run += f;
        float th  = Kthf * (run - 0.5f * (f0f + f));
        float thm = fmaf(0.5f * Kthf, f, th);
        float u = phi0f + thm;
        float u2 = u * u;
        float cu = fmaf(u2, fmaf(u2, 1.f / 24.f, -0.5f), 1.f);
        float su = u * fmaf(u2, fmaf(u2, 1.f / 120.f, -1.f / 6.f), 1.f);
        float qf = (i < N) ? qstepf(Kzf * cu, zf[k]) : 0.f;
        float cx = (i < N) ? Kzf * su : 0.f;
        qs[k] = qf;   Tq += qf;
        cxs[k] = cx;  Tcx += cx;
        fs[k] = th;                            // keep node theta
    }
    float excx; double exq;
    scan_fd(&sm, Tcx, (double)Tq, sid, bg, excx, exq); sid++;

    float Tqx = 0.f, Tqy = 0.f;
    {
        double basez = z0 + exq;
        float bzhi = (float)basez;
        float bzlo = (float)(basez - (double)bzhi);
        float runq = 0.f, runcx = excx;
#pragma unroll
        for (int k = 0; k < EPT; ++k) {
            int i = base + k;
            zf[k] = bzhi + (bzlo + runq);
            runq += qs[k];
            float xpl = x0f + runcx;                 // plain x (binade ref)
            runcx += cxs[k];
            float qx = (i < N) ? qstepf(cxs[k], xpl) : 0.f;
            cxs[k] = qx;  Tqx += qx;
            float ypl = fmaf(cyf, (float)i, y0f);    // plain y (binade ref)
            float qy = (i < N) ? qstepf(cyf, ypl) : 0.f;
            qs[k] = qy;   Tqy += qy;
        }
    }
    float exqx, exqy;
    scan_ff(&sm, Tqx, Tqy, sid, bg, exqx, exqy); sid++;

    // ---- outputs (smem transpose, coalesced, float4 fast path) ----
    const size_t Ns = (size_t)N;
    const int nrem = N - blk0;
    const bool full = (nrem >= TILE) && ((Ns & 3u) == 0) && ((blk0 & 3) == 0);

    // pass 1: x (stage 0), y (stage 1)
    {
        double basex = sm.c.x0 + (double)exqx;
        float bxhi = (float)basex;
        float bxlo = (float)(basex - (double)bxhi);
        double basey = sm.c.y0 + (double)exqy;
        float byhi = (float)basey;
        float bylo = (float)(basey - (double)byhi);
        float runqx = 0.f, runqy = 0.f;
        __syncthreads();
#pragma unroll
        for (int k = 0; k < EPT; ++k) {
            sm.stage[0][tid * EPT + k] = bxhi + (bxlo + runqx);
            sm.stage[1][tid * EPT + k] = byhi + (bylo + runqy);
            runqx += cxs[k];
            runqy += qs[k];
        }
        __syncthreads();
        if (full) {
            const float4* s0 = (const float4*)sm.stage[0];
            const float4* s1 = (const float4*)sm.stage[1];
            float4* o0 = (float4*)(out + blk0);
            float4* o1 = (float4*)(out + Ns + blk0);
            for (int j = tid; j < TILE / 4; j += TPB) { o0[j] = s0[j]; o1[j] = s1[j]; }
        } else {
            for (int j = tid; j < TILE; j += TPB)
                if (j < nrem) { out[blk0 + j] = sm.stage[0][j]; out[Ns + blk0 + j] = sm.stage[1][j]; }
        }
    }
    // pass 2: z (stage 0), beta_y constant direct
    {
        __syncthreads();
#pragma unroll
        for (int k = 0; k < EPT; ++k)
            sm.stage[0][tid * EPT + k] = zf[k];
        __syncthreads();
        if (full) {
            const float4* s0 = (const float4*)sm.stage[0];
            float4* o0 = (float4*)(out + 2 * Ns + blk0);
            float4* o1 = (float4*)(out + 4 * Ns + blk0);
            float4 cv = make_float4(byc, byc, byc, byc);
            for (int j = tid; j < TILE / 4; j += TPB) { o0[j] = s0[j]; o1[j] = cv; }
        } else {
            for (int j = tid; j < TILE; j += TPB)
                if (j < nrem) { out[2 * Ns + blk0 + j] = sm.stage[0][j]; out[4 * Ns + blk0 + j] = byc; }
        }
    }
    // pass 3: beta_x (stage 0), beta_z (stage 1) — share u-poly
    {
        __syncthreads();
#pragma unroll
        for (int k = 0; k < EPT; ++k) {
            float u = phi0f + fs[k];
            float u2 = u * u;
            float su = u * fmaf(u2, fmaf(u2, 1.f / 120.f, -1.f / 6.f), 1.f);
            float cu = fmaf(u2, fmaf(u2, 1.f / 24.f, -0.5f), 1.f);
            sm.stage[0][tid * EPT + k] = scalef * su;
            sm.stage[1][tid * EPT + k] = scalef * cu;
        }
        __syncthreads();
        if (full) {
            const float4* s0 = (const float4*)sm.stage[0];
            const float4* s1 = (const float4*)sm.stage[1];
            float4* o0 = (float4*)(out + 3 * Ns + blk0);
            float4* o1 = (float4*)(out + 5 * Ns + blk0);
            for (int j = tid; j < TILE / 4; j += TPB) { o0[j] = s0[j]; o1[j] = s1[j]; }
        } else {
            for (int j = tid; j < TILE; j += TPB)
                if (j < nrem) { out[3 * Ns + blk0 + j] = sm.stage[0][j]; out[5 * Ns + blk0 + j] = sm.stage[1][j]; }
        }
    }
}

// ---------------- serial fallback (N exceeds capacity) ---------------------
__global__ void __launch_bounds__(32, 1) track_seq_kernel(
    const float* __restrict__ time, const float* __restrict__ r0v,
    const float* __restrict__ d0v, const float* __restrict__ gptr,
    const float* __restrict__ b0ptr, const float* __restrict__ kuptr,
    float* __restrict__ out, int N)
{
    if (threadIdx.x != 0 || blockIdx.x != 0) return;
    const float C = 0.29979245f;
    const float dt = time[1] - time[0];
    const float dt2 = 0.5f * dt, h6 = dt * (1.0f / 6.0f);
    const float gamma = gptr[0], B0 = b0ptr[0], ku = kuptr[0];
    const float A = 1.0f / gamma;
    const float KdtA2 = ku * dt2 * A, KdtA = ku * dt * A;
    const float inv_cg = 1.0f / (C * gamma);
    float dx0 = d0v[0], dy0 = d0v[1], dz0 = d0v[2];
    float dn = sqrtf(dx0 * dx0 + dy0 * dy0 + dz0 * dz0);
    float pscale = C * sqrtf(gamma * gamma - 1.0f) / dn;
    float px = pscale * dx0, py = pscale * dy0, pz = pscale * dz0;
    float x = r0v[0], y = r0v[1], z = r0v[2];
    const float vy = py * A;
    float cps = cosf(ku * z), sps = sinf(ku * z);
    float Bc = B0 * cps, Bs = B0 * sps;
    const size_t Ns = (size_t)N;
    out[0] = x; out[Ns] = y; out[2 * Ns] = z;
    out[3 * Ns] = px * inv_cg; out[4 * Ns] = py * inv_cg; out[5 * Ns] = pz * inv_cg;
#pragma unroll 1
    for (int i = 1; i < N; ++i) {
        float vx1 = px * A, vz1 = pz * A;
        float apx1 = pz * Bc * A, apz1 = -px * Bc * A;
        float px2 = fmaf(apx1, dt2, px), pz2 = fmaf(apz1, dt2, pz);
        float d2 = KdtA2 * pz, q2 = d2 * d2;
        float sd2 = d2 * fmaf(-0.16666667f, q2, 1.0f), cd2 = fmaf(-0.5f, q2, 1.0f);
        float By2 = fmaf(Bc, cd2, -Bs * sd2);
        float vx2 = px2 * A, vz2 = pz2 * A;
        float apx2 = pz2 * By2 * A, apz2 = -px2 * By2 * A;
        float px3 = fmaf(apx2, dt2, px), pz3 = fmaf(apz2, dt2, pz);
        float d3 = KdtA2 * pz2, q3 = d3 * d3;
        float sd3 = d3 * fmaf(-0.16666667f, q3, 1.0f), cd3 = fmaf(-0.5f, q3, 1.0f);
        float By3 = fmaf(Bc, cd3, -Bs * sd3);
        float vx3 = px3 * A, vz3 = pz3 * A;
        float apx3 = pz3 * By3 * A, apz3 = -px3 * By3 * A;
        float px4 = fmaf(apx3, dt, px), pz4 = fmaf(apz3, dt, pz);
        float d4 = KdtA * pz3, q4 = d4 * d4;
        float sd4 = d4 * fmaf(-0.16666667f, q4, 1.0f), cd4 = fmaf(-0.5f, q4, 1.0f);
        float By4 = fmaf(Bc, cd4, -Bs * sd4);
        float vx4 = px4 * A, vz4 = pz4 * A;
        float apx4 = pz4 * By4 * A, apz4 = -px4 * By4 * A;
        float dxs = h6 * (vx1 + 2.0f * (vx2 + vx3) + vx4);
        float dzs = h6 * (vz1 + 2.0f * (vz2 + vz3) + vz4);
        px = px + h6 * (apx1 + 2.0f * (apx2 + apx3) + apx4);
        pz = pz + h6 * (apz1 + 2.0f * (apz2 + apz3) + apz4);
        x += dxs; y += dt * vy; z += dzs;
        float dp = ku * dzs, qp = dp * dp;
        float sdp = dp * fmaf(-0.16666667f, qp, 1.0f), cdp = fmaf(-0.5f, qp, 1.0f);
        float cn = fmaf(cps, cdp, -sps * sdp);
        float sn = fmaf(sps, cdp, cps * sdp);
        float nr = fmaf(cn, cn, sn * sn);
        float corr = fmaf(-0.5f, nr, 1.5f);
        cps = cn * corr; sps = sn * corr;
        Bc = B0 * cps; Bs = B0 * sps;
        out[i] = x; out[Ns + i] = y; out[2 * Ns + i] = z;
        out[3 * Ns + i] = px * inv_cg; out[4 * Ns + i] = py * inv_cg; out[5 * Ns + i] = pz * inv_cg;
    }
}

extern "C" void kernel_launch(void* const* d_in, const int* in_sizes, int n_in,
                              void* d_out, int out_size) {
    const float* time = (const float*)d_in[0];
    const float* r0   = (const float*)d_in[1];
    const float* d0   = (const float*)d_in[2];
    const float* gam  = (const float*)d_in[3];
    const float* B0   = (const float*)d_in[4];
    const float* ku   = (const float*)d_in[5];
    float* out = (float*)d_out;
    int N = in_sizes[0];

    if (N > CAP) {
        track_seq_kernel<<<1, 32>>>(time, r0, d0, gam, B0, ku, out, N);
        return;
    }
    picard_all<<<GRD, TPB>>>(time, r0, d0, gam, B0, ku, out, N);
}